// round 12
// baseline (speedup 1.0000x reference)
#include <cuda_runtime.h>
#include <cuda_fp16.h>
#include <cuda_bf16.h>
#include <cstdint>

#define NBATCH 2
#define SLEN   2048
#define HDIM   2048
#define NH     16
#define NKV    8
#define HD     128
#define TTOK   (NBATCH*SLEN)          /* 4096 */
#define BH     (NBATCH*NH)            /* 32 */
#define KVW    (NKV*HD)               /* 1024 */
#define OWID   (NH*HD)                /* 2048 */
#define SCALEF 0.08838834764831845f
#define EPSF   1e-6f
#define NCH    16
#define CHS    (SLEN/NCH)             /* 128 */

// ------------------------- device scratch (no runtime alloc) ---------------
__device__ float g_qraw[(size_t)TTOK * (2*OWID)];
__device__ float g_kraw[(size_t)TTOK * KVW];
__device__ float g_vraw[(size_t)TTOK * KVW];
__device__ float g_q   [(size_t)BH * SLEN * HD];
__device__ float g_gate[(size_t)TTOK * OWID];
__device__ float g_vsuf[(size_t)NBATCH * NKV * SLEN * HD];
__device__ float g_csum[(size_t)NBATCH * NKV * NCH * HD];
__device__ float g_sm  [(size_t)BH * SLEN];
__device__ float g_sid [(size_t)BH * SLEN];
__device__ float g_sc  [(size_t)BH * SLEN];
__device__ float g_ao  [(size_t)TTOK * OWID];

// ----------------------------- helpers -------------------------------------
__device__ __forceinline__ uint32_t smem_u32(const void* p) {
    uint32_t a;
    asm("{ .reg .u64 t; cvta.to.shared.u64 t, %1; cvt.u32.u64 %0, t; }" : "=r"(a) : "l"(p));
    return a;
}

#define LDMX4(r, a) \
    asm volatile("ldmatrix.sync.aligned.m8n8.x4.shared.b16 {%0,%1,%2,%3}, [%4];" \
        : "=r"((r)[0]), "=r"((r)[1]), "=r"((r)[2]), "=r"((r)[3]) : "r"(a))

#define MMA16816(d, a, b) \
    asm volatile("mma.sync.aligned.m16n8k16.row.col.f32.f16.f16.f32 " \
        "{%0,%1,%2,%3}, {%4,%5,%6,%7}, {%8,%9}, {%0,%1,%2,%3};" \
        : "+f"((d)[0]), "+f"((d)[1]), "+f"((d)[2]), "+f"((d)[3]) \
        : "r"((a)[0]), "r"((a)[1]), "r"((a)[2]), "r"((a)[3]), \
          "r"((b)[0]), "r"((b)[1]))

// fp32x4 -> fp16 hi/lo split (hi + lo ~ 22-bit mantissa effective)
__device__ __forceinline__ void split4h(float4 v, uint2& hi, uint2& lo) {
    __half2 h01 = __floats2half2_rn(v.x, v.y);
    __half2 h23 = __floats2half2_rn(v.z, v.w);
    float2 f01 = __half22float2(h01), f23 = __half22float2(h23);
    __half2 l01 = __floats2half2_rn(v.x - f01.x, v.y - f01.y);
    __half2 l23 = __floats2half2_rn(v.z - f23.x, v.w - f23.y);
    hi.x = *reinterpret_cast<uint32_t*>(&h01);
    hi.y = *reinterpret_cast<uint32_t*>(&h23);
    lo.x = *reinterpret_cast<uint32_t*>(&l01);
    lo.y = *reinterpret_cast<uint32_t*>(&l23);
}

// --------- HMMA GEMM: C[M,N] = A[M,K] @ W[N,K]^T, fp16x3 split -------------
// 128x128 tile/CTA, 8 warps (4M x 2N), K-chunks of 64, double-buffered SMEM.
// Per-buffer layout: Ahi @0, Alo @16K, Whi @32K, Wlo @48K (fp16, SW128).
#define GBUF 65536
__global__ __launch_bounds__(256, 1) void gemm_tc(const float* __restrict__ A,
                                                  const float* __restrict__ W,
                                                  float* __restrict__ C,
                                                  int M, int N, int K) {
    extern __shared__ __align__(1024) char smem[];
    const int tid = threadIdx.x, wid = tid >> 5, lane = tid & 31;
    const int bm = blockIdx.y * 128, bn = blockIdx.x * 128;
    const int m0w = (wid & 3) * 32, n0w = (wid >> 2) * 64;
    const uint32_t sbase = smem_u32(smem);

    float acc[2][8][4];
#pragma unroll
    for (int mt = 0; mt < 2; ++mt)
#pragma unroll
        for (int nt = 0; nt < 8; ++nt)
#pragma unroll
            for (int q = 0; q < 4; ++q) acc[mt][nt][q] = 0.f;

    auto fill = [&](int buf, int k0) {
        char* bb = smem + (size_t)buf * GBUF;
#pragma unroll
        for (int it = 0; it < 8; ++it) {
            int slot = it * 256 + tid;
            int row = slot >> 4, c4 = slot & 15;          // 16 float4 per row
            uint32_t off = (uint32_t)row * 128 + c4 * 8;  // fp16 tile byte offset
            uint32_t sw = off ^ ((off >> 3) & 0x70);
            float4 va = *reinterpret_cast<const float4*>(A + (size_t)(bm + row) * K + k0 + c4 * 4);
            uint2 h, l; split4h(va, h, l);
            *reinterpret_cast<uint2*>(bb + sw)         = h;
            *reinterpret_cast<uint2*>(bb + 16384 + sw) = l;
            float4 vw = *reinterpret_cast<const float4*>(W + (size_t)(bn + row) * K + k0 + c4 * 4);
            split4h(vw, h, l);
            *reinterpret_cast<uint2*>(bb + 32768 + sw) = h;
            *reinterpret_cast<uint2*>(bb + 49152 + sw) = l;
        }
    };

    auto compute = [&](int buf) {
        const uint32_t base = sbase + buf * GBUF;
#pragma unroll
        for (int ks = 0; ks < 4; ++ks) {
            uint32_t ah[2][4], al[2][4], bh[8][2], bl[8][2];
#pragma unroll
            for (int mt = 0; mt < 2; ++mt) {
                uint32_t off = (uint32_t)(m0w + mt * 16 + (lane & 15)) * 128
                             + ((lane >> 4) << 4) + ks * 32;
                uint32_t sw = base + (off ^ ((off >> 3) & 0x70));
                LDMX4(ah[mt], sw);
                LDMX4(al[mt], sw + 16384);
            }
#pragma unroll
            for (int nt2 = 0; nt2 < 4; ++nt2) {
                uint32_t off = (uint32_t)(n0w + nt2 * 16 + (lane & 7) + ((lane >> 4) << 3)) * 128
                             + (((lane >> 3) & 1) << 4) + ks * 32;
                uint32_t sw = base + (off ^ ((off >> 3) & 0x70));
                uint32_t r[4];
                LDMX4(r, sw + 32768);
                bh[nt2*2][0] = r[0]; bh[nt2*2][1] = r[1];
                bh[nt2*2+1][0] = r[2]; bh[nt2*2+1][1] = r[3];
                LDMX4(r, sw + 49152);
                bl[nt2*2][0] = r[0]; bl[nt2*2][1] = r[1];
                bl[nt2*2+1][0] = r[2]; bl[nt2*2+1][1] = r[3];
            }
#pragma unroll
            for (int mt = 0; mt < 2; ++mt)
#pragma unroll
                for (int nt = 0; nt < 8; ++nt) {
                    MMA16816(acc[mt][nt], ah[mt], bh[nt]);
                    MMA16816(acc[mt][nt], ah[mt], bl[nt]);
                    MMA16816(acc[mt][nt], al[mt], bh[nt]);
                }
        }
    };

    fill(0, 0);
    const int NC = K / 64;
    for (int kt = 0; kt < NC; ++kt) {
        __syncthreads();
        compute(kt & 1);
        if (kt + 1 < NC) fill((kt + 1) & 1, (kt + 1) * 64);
    }

    // epilogue: D frag -> C
#pragma unroll
    for (int mt = 0; mt < 2; ++mt)
#pragma unroll
        for (int nt = 0; nt < 8; ++nt) {
            const int r0 = bm + m0w + mt * 16 + (lane >> 2);
            const int c0 = bn + n0w + nt * 8 + (lane & 3) * 2;
            float2 v0 = make_float2(acc[mt][nt][0], acc[mt][nt][1]);
            float2 v1 = make_float2(acc[mt][nt][2], acc[mt][nt][3]);
            *reinterpret_cast<float2*>(C + (size_t)r0 * N + c0)       = v0;
            *reinterpret_cast<float2*>(C + (size_t)(r0 + 8) * N + c0) = v1;
        }
}
#define GEMM_SMEM (2*GBUF)

// ------------------- Q post: RMSNorm + RoPE, split gate --------------------
__global__ __launch_bounds__(128) void postq(const float* __restrict__ cosb,
                                             const float* __restrict__ sinb,
                                             const float* __restrict__ qw) {
    const int idx = blockIdx.x;
    const int h = idx % NH;
    const int bs = idx / NH;
    const int d = threadIdx.x;
    const float* row = g_qraw + (size_t)bs * (2*OWID) + (size_t)h * (2*HD);
    float x = row[d];
    float g = row[HD + d];
    float v = x * x;
#pragma unroll
    for (int o = 16; o >= 1; o >>= 1) v += __shfl_xor_sync(0xffffffffu, v, o);
    __shared__ float red[4];
    __shared__ float buf[HD];
    if ((d & 31) == 0) red[d >> 5] = v;
    __syncthreads();
    float ss = red[0] + red[1] + red[2] + red[3];
    float r = rsqrtf(ss * (1.f / HD) + EPSF);
    float xn = x * r * qw[d];
    buf[d] = xn;
    __syncthreads();
    float other = (d < 64) ? -buf[d + 64] : buf[d - 64];
    float c = cosb[(size_t)bs * HD + d];
    float sn = sinb[(size_t)bs * HD + d];
    float q = xn * c + other * sn;
    const int b = bs >> 11, s = bs & (SLEN - 1);
    g_q[(((size_t)b * NH + h) * SLEN + s) * HD + d] = q;
    g_gate[(size_t)bs * OWID + (size_t)h * HD + d] = g;
}

// ------------------- K post: RMSNorm + RoPE in place -----------------------
__global__ __launch_bounds__(128) void postk(const float* __restrict__ cosb,
                                             const float* __restrict__ sinb,
                                             const float* __restrict__ kw) {
    const int idx = blockIdx.x;
    const int kh = idx % NKV;
    const int bs = idx / NKV;
    const int d = threadIdx.x;
    float* row = g_kraw + (size_t)bs * KVW + (size_t)kh * HD;
    float x = row[d];
    float v = x * x;
#pragma unroll
    for (int o = 16; o >= 1; o >>= 1) v += __shfl_xor_sync(0xffffffffu, v, o);
    __shared__ float red[4];
    __shared__ float buf[HD];
    if ((d & 31) == 0) red[d >> 5] = v;
    __syncthreads();
    float ss = red[0] + red[1] + red[2] + red[3];
    float r = rsqrtf(ss * (1.f / HD) + EPSF);
    float xn = x * r * kw[d];
    buf[d] = xn;
    __syncthreads();
    float other = (d < 64) ? -buf[d + 64] : buf[d - 64];
    float c = cosb[(size_t)bs * HD + d];
    float sn = sinb[(size_t)bs * HD + d];
    row[d] = xn * c + other * sn;
}

// ------------------------------ V suffix sums -------------------------------
__global__ __launch_bounds__(128) void vsuf_chunks() {
    const int blk = blockIdx.x;
    const int ch = blk % NCH;
    const int bk = blk / NCH;
    const int kh = bk % NKV, b = bk / NKV;
    const int d = threadIdx.x;
    float acc = 0.f;
    const int j0 = ch * CHS;
    for (int jj = 0; jj < CHS; ++jj)
        acc += g_vraw[(((size_t)b * SLEN + j0 + jj) * NKV + kh) * HD + d];
    g_csum[((size_t)bk * NCH + ch) * HD + d] = acc;
}

__global__ __launch_bounds__(128) void vsuf_write() {
    const int blk = blockIdx.x;
    const int ch = blk % NCH;
    const int bk = blk / NCH;
    const int kh = bk % NKV, b = bk / NKV;
    const int d = threadIdx.x;
    float acc = 0.f;
    for (int c = ch + 1; c < NCH; ++c)
        acc += g_csum[((size_t)bk * NCH + c) * HD + d];
    for (int jj = CHS - 1; jj >= 0; --jj) {
        const int j = ch * CHS + jj;
        g_vsuf[((size_t)bk * SLEN + j) * HD + d] = acc;
        acc += g_vraw[(((size_t)b * SLEN + j) * NKV + kh) * HD + d];
    }
}

// -------- pass A: scores -> attn scratch (causal tiles) + row stats ---------
__global__ __launch_bounds__(256, 1) void attn_pass_a(float* __restrict__ attn) {
    extern __shared__ float smemf[];
    float* qsm = smemf;
    float* ksm = smemf + 16384;
    const int tid = threadIdx.x, tx = tid & 15, ty = tid >> 4;
    const int qt = blockIdx.x, bh = blockIdx.y;
    const int b = bh >> 4, h = bh & 15, kh = h >> 1;
    const int qi0 = qt * 128;

    const float* qb = g_q + ((size_t)bh * SLEN + qi0) * HD;
#pragma unroll
    for (int it = 0; it < 16; ++it) {
        int slot = it * 256 + tid;
        int r = slot & 127, d4 = (slot >> 7) * 4;
        float4 v = *reinterpret_cast<const float4*>(qb + (size_t)r * HD + d4);
        qsm[(d4+0)*128+r]=v.x; qsm[(d4+1)*128+r]=v.y; qsm[(d4+2)*128+r]=v.z; qsm[(d4+3)*128+r]=v.w;
    }
    float run_m[8], run_l[8], run_mn[8];
#pragma unroll
    for (int i = 0; i < 8; ++i) { run_m[i] = -1e30f; run_l[i] = 0.f; run_mn[i] = 1e30f; }

    const float* kb = g_kraw + (size_t)b * SLEN * KVW + (size_t)kh * HD;
    for (int kt = 0; kt < SLEN/128; ++kt) {
        const int kj0 = kt * 128;
        __syncthreads();
#pragma unroll
        for (int it = 0; it < 16; ++it) {
            int slot = it * 256 + tid;
            int c = slot & 127, d4 = (slot >> 7) * 4;
            float4 v = *reinterpret_cast<const float4*>(kb + (size_t)(kj0 + c) * KVW + d4);
            ksm[(d4+0)*128+c]=v.x; ksm[(d4+1)*128+c]=v.y; ksm[(d4+2)*128+c]=v.z; ksm[(d4+3)*128+c]=v.w;
        }
        __syncthreads();
        float acc[8][8];
#pragma unroll
        for (int i = 0; i < 8; ++i)
#pragma unroll
            for (int j = 0; j < 8; ++j) acc[i][j] = 0.f;
#pragma unroll 4
        for (int k = 0; k < 128; ++k) {
            float a[8], bb[8];
            *reinterpret_cast<float4*>(&a[0])  = *reinterpret_cast<const float4*>(&qsm[k*128 + ty*8]);
            *reinterpret_cast<float4*>(&a[4])  = *reinterpret_cast<const float4*>(&qsm[k*128 + ty*8 + 4]);
            *reinterpret_cast<float4*>(&bb[0]) = *reinterpret_cast<const float4*>(&ksm[k*128 + tx*8]);
            *reinterpret_cast<float4*>(&bb[4]) = *reinterpret_cast<const float4*>(&ksm[k*128 + tx*8 + 4]);
#pragma unroll
            for (int i = 0; i < 8; ++i)
#pragma unroll
                for (int j = 0; j < 8; ++j) acc[i][j] = fmaf(a[i], bb[j], acc[i][j]);
        }
        const bool diag = (kt == qt), caus = (kt < qt);
#pragma unroll
        for (int ii = 0; ii < 8; ++ii) {
            const int i = qi0 + ty*8 + ii;
            float s[8]; float vmx = -1e30f, vmn = 1e30f;
#pragma unroll
            for (int jj = 0; jj < 8; ++jj) {
                s[jj] = acc[ii][jj] * SCALEF;
                vmn = fminf(vmn, s[jj]);
                bool val = caus || (diag && (kj0 + tx*8 + jj) <= i);
                if (val) vmx = fmaxf(vmx, s[jj]);
            }
#pragma unroll
            for (int o = 8; o >= 1; o >>= 1) {
                vmx = fmaxf(vmx, __shfl_xor_sync(0xffffffffu, vmx, o));
                vmn = fminf(vmn, __shfl_xor_sync(0xffffffffu, vmn, o));
            }
            run_mn[ii] = fminf(run_mn[ii], vmn);
            if (caus || diag) {
                float tl = 0.f;
#pragma unroll
                for (int jj = 0; jj < 8; ++jj) {
                    bool val = caus || ((kj0 + tx*8 + jj) <= i);
                    if (val) tl += __expf(s[jj] - vmx);
                }
#pragma unroll
                for (int o = 8; o >= 1; o >>= 1) tl += __shfl_xor_sync(0xffffffffu, tl, o);
                float nm = fmaxf(run_m[ii], vmx);
                run_l[ii] = run_l[ii] * __expf(run_m[ii] - nm) + tl * __expf(vmx - nm);
                run_m[ii] = nm;
                float* arow = attn + ((size_t)bh * SLEN + i) * SLEN + kj0 + tx*8;
                *reinterpret_cast<float4*>(arow)   = make_float4(s[0],s[1],s[2],s[3]);
                *reinterpret_cast<float4*>(arow+4) = make_float4(s[4],s[5],s[6],s[7]);
            }
        }
    }
    if (tx == 0) {
#pragma unroll
        for (int ii = 0; ii < 8; ++ii) {
            const int i = qi0 + ty*8 + ii;
            float m = run_m[ii];
            float e = __expf(run_mn[ii] - 20.f - m);
            float L = run_l[ii] + (float)(SLEN - 1 - i) * e;
            float id = 1.f / L;
            g_sm [(size_t)bh * SLEN + i] = m;
            g_sid[(size_t)bh * SLEN + i] = id;
            g_sc [(size_t)bh * SLEN + i] = e * id;
        }
    }
}

// -------- fill fully-masked tiles with per-row constant ---------------------
__global__ __launch_bounds__(256) void fill_masked(float* __restrict__ attn) {
    const int qt = blockIdx.x, bh = blockIdx.y;
    const int i0 = qt * 128, c0 = (qt + 1) * 128;
    const int nc4 = (SLEN - c0) >> 2;
    for (int r = 0; r < 128; ++r) {
        const int i = i0 + r;
        float c = g_sc[(size_t)bh * SLEN + i];
        float4 cv = make_float4(c, c, c, c);
        float4* row = reinterpret_cast<float4*>(attn + ((size_t)bh * SLEN + i) * SLEN + c0);
        for (int x = threadIdx.x; x < nc4; x += 256) row[x] = cv;
    }
}

// -------- pass B: finalize probs on causal tiles + PV + gate ----------------
__global__ __launch_bounds__(256, 1) void attn_pass_b(float* __restrict__ attn) {
    extern __shared__ float smemf[];
    float* ps = smemf;
    float* vs = smemf + 16384;
    const int tid = threadIdx.x, tx = tid & 15, ty = tid >> 4;
    const int qt = blockIdx.x, bh = blockIdx.y;
    const int b = bh >> 4, h = bh & 15, kh = h >> 1;
    const int qi0 = qt * 128;

    float m8[8], id8[8], c8[8];
#pragma unroll
    for (int ii = 0; ii < 8; ++ii) {
        size_t ri = (size_t)bh * SLEN + qi0 + ty*8 + ii;
        m8[ii] = g_sm[ri]; id8[ii] = g_sid[ri]; c8[ii] = g_sc[ri];
    }
    float acc[8][8];
#pragma unroll
    for (int i = 0; i < 8; ++i)
#pragma unroll
        for (int j = 0; j < 8; ++j) acc[i][j] = 0.f;

    const float* vb = g_vraw + (size_t)b * SLEN * KVW + (size_t)kh * HD;
    for (int kt = 0; kt <= qt; ++kt) {
        const int kj0 = kt * 128;
        __syncthreads();
#pragma unroll
        for (int it = 0; it < 16; ++it) {
            int slot = it * 256 + tid;
            int c = slot >> 5, d4 = (slot & 31) * 4;
            *reinterpret_cast<float4*>(&vs[c*128 + d4]) =
                *reinterpret_cast<const float4*>(vb + (size_t)(kj0 + c) * KVW + d4);
        }
        const bool diag = (kt == qt);
#pragma unroll
        for (int ii = 0; ii < 8; ++ii) {
            const int i = qi0 + ty*8 + ii;
            float* arow = attn + ((size_t)bh * SLEN + i) * SLEN + kj0 + tx*8;
            float4 s0 = *reinterpret_cast<const float4*>(arow);
            float4 s1 = *reinterpret_cast<const float4*>(arow + 4);
            float sv[8] = {s0.x, s0.y, s0.z, s0.w, s1.x, s1.y, s1.z, s1.w};
            float pw[8], pp[8];
#pragma unroll
            for (int jj = 0; jj < 8; ++jj) {
                float e = __expf(sv[jj] - m8[ii]) * id8[ii];
                bool val = !diag || ((kj0 + tx*8 + jj) <= i);
                pw[jj] = val ? e : c8[ii];
                pp[jj] = val ? e : 0.f;
            }
            *reinterpret_cast<float4*>(arow)   = make_float4(pw[0],pw[1],pw[2],pw[3]);
            *reinterpret_cast<float4*>(arow+4) = make_float4(pw[4],pw[5],pw[6],pw[7]);
            float* prow = &ps[(ty*8 + ii) * 128 + tx*8];
            *reinterpret_cast<float4*>(prow)   = make_float4(pp[0],pp[1],pp[2],pp[3]);
            *reinterpret_cast<float4*>(prow+4) = make_float4(pp[4],pp[5],pp[6],pp[7]);
        }
        __syncthreads();
#pragma unroll 4
        for (int j = 0; j < 128; ++j) {
            float a[8], bb[8];
#pragma unroll
            for (int ii = 0; ii < 8; ++ii) a[ii] = ps[(ty*8 + ii) * 128 + j];
            *reinterpret_cast<float4*>(&bb[0]) = *reinterpret_cast<const float4*>(&vs[j*128 + tx*8]);
            *reinterpret_cast<float4*>(&bb[4]) = *reinterpret_cast<const float4*>(&vs[j*128 + tx*8 + 4]);
#pragma unroll
            for (int ii = 0; ii < 8; ++ii)
#pragma unroll
                for (int dd = 0; dd < 8; ++dd) acc[ii][dd] = fmaf(a[ii], bb[dd], acc[ii][dd]);
        }
    }
#pragma unroll
    for (int ii = 0; ii < 8; ++ii) {
        const int i = qi0 + ty*8 + ii;
        const float* vsf  = g_vsuf + (((size_t)(b * NKV + kh)) * SLEN + i) * HD + tx*8;
        const float* grow = g_gate + ((size_t)b * SLEN + i) * OWID + (size_t)h * HD + tx*8;
        float*       orow = g_ao   + ((size_t)b * SLEN + i) * OWID + (size_t)h * HD + tx*8;
        float o[8];
#pragma unroll
        for (int dd = 0; dd < 8; ++dd) {
            float val = acc[ii][dd] + c8[ii] * vsf[dd];
            o[dd] = val / (1.f + __expf(-grow[dd]));
        }
        *reinterpret_cast<float4*>(orow)   = make_float4(o[0],o[1],o[2],o[3]);
        *reinterpret_cast<float4*>(orow+4) = make_float4(o[4],o[5],o[6],o[7]);
    }
}

// ----------------------------------------------------------------------------
extern "C" void kernel_launch(void* const* d_in, const int* in_sizes, int n_in,
                              void* d_out, int out_size) {
    const float* hidden = (const float*)d_in[0];
    const float* cosb   = (const float*)d_in[1];
    const float* sinb   = (const float*)d_in[2];
    const float* Wq     = (const float*)d_in[4];
    const float* Wk     = (const float*)d_in[5];
    const float* Wv     = (const float*)d_in[6];
    const float* Wo     = (const float*)d_in[7];
    const float* qnw    = (const float*)d_in[8];
    const float* knw    = (const float*)d_in[9];

    float* out_ptr  = (float*)d_out;
    float* attn_ptr = out_ptr + (size_t)NBATCH * SLEN * HDIM;

    float *p_qraw, *p_kraw, *p_vraw, *p_ao;
    cudaGetSymbolAddress((void**)&p_qraw, g_qraw);
    cudaGetSymbolAddress((void**)&p_kraw, g_kraw);
    cudaGetSymbolAddress((void**)&p_vraw, g_vraw);
    cudaGetSymbolAddress((void**)&p_ao,   g_ao);

    cudaFuncSetAttribute(gemm_tc,     cudaFuncAttributeMaxDynamicSharedMemorySize, GEMM_SMEM);
    cudaFuncSetAttribute(attn_pass_a, cudaFuncAttributeMaxDynamicSharedMemorySize, 131072);
    cudaFuncSetAttribute(attn_pass_b, cudaFuncAttributeMaxDynamicSharedMemorySize, 131072);

    // QKV projections (HMMA fp16x3)
    gemm_tc<<<dim3(2*OWID/128, TTOK/128), 256, GEMM_SMEM>>>(hidden, Wq, p_qraw, TTOK, 2*OWID, HDIM);
    gemm_tc<<<dim3(KVW/128,    TTOK/128), 256, GEMM_SMEM>>>(hidden, Wk, p_kraw, TTOK, KVW,    HDIM);
    gemm_tc<<<dim3(KVW/128,    TTOK/128), 256, GEMM_SMEM>>>(hidden, Wv, p_vraw, TTOK, KVW,    HDIM);

    // norms + rope + gate split
    postq<<<TTOK * NH,  128>>>(cosb, sinb, qnw);
    postk<<<TTOK * NKV, 128>>>(cosb, sinb, knw);

    // V suffix sums
    vsuf_chunks<<<NBATCH * NKV * NCH, 128>>>();
    vsuf_write <<<NBATCH * NKV * NCH, 128>>>();

    // attention
    attn_pass_a<<<dim3(SLEN/128, BH), 256, 131072>>>(attn_ptr);
    fill_masked<<<dim3(SLEN/128 - 1, BH), 256>>>(attn_ptr);
    attn_pass_b<<<dim3(SLEN/128, BH), 256, 131072>>>(attn_ptr);

    // output projection (HMMA fp16x3)
    gemm_tc<<<dim3(HDIM/128, TTOK/128), 256, GEMM_SMEM>>>(p_ao, Wo, out_ptr, TTOK, HDIM, OWID);
}

// round 13
// speedup vs baseline: 1.5639x; 1.5639x over previous
#include <cuda_runtime.h>
#include <cuda_fp16.h>
#include <cuda_bf16.h>
#include <cstdint>

#define NBATCH 2
#define SLEN   2048
#define HDIM   2048
#define NH     16
#define NKV    8
#define HD     128
#define TTOK   (NBATCH*SLEN)          /* 4096 */
#define BH     (NBATCH*NH)            /* 32 */
#define KVW    (NKV*HD)               /* 1024 */
#define OWID   (NH*HD)                /* 2048 */
#define SCALEF 0.08838834764831845f
#define EPSF   1e-6f
#define NCH    16
#define CHS    (SLEN/NCH)             /* 128 */

// ------------------------- device scratch (no runtime alloc) ---------------
__device__ float g_qraw[(size_t)TTOK * (2*OWID)];
__device__ float g_kraw[(size_t)TTOK * KVW];
__device__ float g_vraw[(size_t)TTOK * KVW];
__device__ float g_q   [(size_t)BH * SLEN * HD];
__device__ float g_gate[(size_t)TTOK * OWID];
__device__ float g_vsuf[(size_t)NBATCH * NKV * SLEN * HD];
__device__ float g_csum[(size_t)NBATCH * NKV * NCH * HD];
__device__ float g_sm  [(size_t)BH * SLEN];
__device__ float g_sid [(size_t)BH * SLEN];
__device__ float g_sc  [(size_t)BH * SLEN];
__device__ float g_ao  [(size_t)TTOK * OWID];

// ----------------------------- helpers -------------------------------------
__device__ __forceinline__ uint32_t smem_u32(const void* p) {
    uint32_t a;
    asm("{ .reg .u64 t; cvta.to.shared.u64 t, %1; cvt.u32.u64 %0, t; }" : "=r"(a) : "l"(p));
    return a;
}

#define LDMX4(r, a) \
    asm volatile("ldmatrix.sync.aligned.m8n8.x4.shared.b16 {%0,%1,%2,%3}, [%4];" \
        : "=r"((r)[0]), "=r"((r)[1]), "=r"((r)[2]), "=r"((r)[3]) : "r"(a))

#define MMA16816(d, a, b) \
    asm volatile("mma.sync.aligned.m16n8k16.row.col.f32.f16.f16.f32 " \
        "{%0,%1,%2,%3}, {%4,%5,%6,%7}, {%8,%9}, {%0,%1,%2,%3};" \
        : "+f"((d)[0]), "+f"((d)[1]), "+f"((d)[2]), "+f"((d)[3]) \
        : "r"((a)[0]), "r"((a)[1]), "r"((a)[2]), "r"((a)[3]), \
          "r"((b)[0]), "r"((b)[1]))

// fp32x4 -> fp16 hi/lo split (hi + lo ~ 22-bit mantissa effective)
__device__ __forceinline__ void split4h(float4 v, uint2& hi, uint2& lo) {
    __half2 h01 = __floats2half2_rn(v.x, v.y);
    __half2 h23 = __floats2half2_rn(v.z, v.w);
    float2 f01 = __half22float2(h01), f23 = __half22float2(h23);
    __half2 l01 = __floats2half2_rn(v.x - f01.x, v.y - f01.y);
    __half2 l23 = __floats2half2_rn(v.z - f23.x, v.w - f23.y);
    hi.x = *reinterpret_cast<uint32_t*>(&h01);
    hi.y = *reinterpret_cast<uint32_t*>(&h23);
    lo.x = *reinterpret_cast<uint32_t*>(&l01);
    lo.y = *reinterpret_cast<uint32_t*>(&l23);
}

// --------- HMMA GEMM: C[M,N] = A[M,K] @ W[N,K]^T, fp16x3 split -------------
// 128x128 tile/CTA, 8 warps (4M x 2N), K-chunks of 64, double-buffered SMEM.
// Per-buffer layout: Ahi @0, Alo @16K, Whi @32K, Wlo @48K (fp16, SW128).
#define GBUF 65536
__global__ __launch_bounds__(256, 1) void gemm_tc(const float* __restrict__ A,
                                                  const float* __restrict__ W,
                                                  float* __restrict__ C,
                                                  int M, int N, int K) {
    extern __shared__ __align__(1024) char smem[];
    const int tid = threadIdx.x, wid = tid >> 5, lane = tid & 31;
    const int bm = blockIdx.y * 128, bn = blockIdx.x * 128;
    const int m0w = (wid & 3) * 32, n0w = (wid >> 2) * 64;
    const uint32_t sbase = smem_u32(smem);

    float acc[2][8][4];
#pragma unroll
    for (int mt = 0; mt < 2; ++mt)
#pragma unroll
        for (int nt = 0; nt < 8; ++nt)
#pragma unroll
            for (int q = 0; q < 4; ++q) acc[mt][nt][q] = 0.f;

    auto fill = [&](int buf, int k0) {
        char* bb = smem + (size_t)buf * GBUF;
#pragma unroll
        for (int it = 0; it < 8; ++it) {
            int slot = it * 256 + tid;
            int row = slot >> 4, c4 = slot & 15;          // 16 float4 per row
            uint32_t off = (uint32_t)row * 128 + c4 * 8;  // fp16 tile byte offset
            uint32_t sw = off ^ ((off >> 3) & 0x70);
            float4 va = *reinterpret_cast<const float4*>(A + (size_t)(bm + row) * K + k0 + c4 * 4);
            uint2 h, l; split4h(va, h, l);
            *reinterpret_cast<uint2*>(bb + sw)         = h;
            *reinterpret_cast<uint2*>(bb + 16384 + sw) = l;
            float4 vw = *reinterpret_cast<const float4*>(W + (size_t)(bn + row) * K + k0 + c4 * 4);
            split4h(vw, h, l);
            *reinterpret_cast<uint2*>(bb + 32768 + sw) = h;
            *reinterpret_cast<uint2*>(bb + 49152 + sw) = l;
        }
    };

    auto compute = [&](int buf) {
        const uint32_t base = sbase + buf * GBUF;
#pragma unroll
        for (int ks = 0; ks < 4; ++ks) {
            uint32_t ah[2][4], al[2][4], bh[8][2], bl[8][2];
#pragma unroll
            for (int mt = 0; mt < 2; ++mt) {
                uint32_t off = (uint32_t)(m0w + mt * 16 + (lane & 15)) * 128
                             + ((lane >> 4) << 4) + ks * 32;
                uint32_t sw = base + (off ^ ((off >> 3) & 0x70));
                LDMX4(ah[mt], sw);
                LDMX4(al[mt], sw + 16384);
            }
#pragma unroll
            for (int nt2 = 0; nt2 < 4; ++nt2) {
                uint32_t off = (uint32_t)(n0w + nt2 * 16 + (lane & 7) + ((lane >> 4) << 3)) * 128
                             + (((lane >> 3) & 1) << 4) + ks * 32;
                uint32_t sw = base + (off ^ ((off >> 3) & 0x70));
                uint32_t r[4];
                LDMX4(r, sw + 32768);
                bh[nt2*2][0] = r[0]; bh[nt2*2][1] = r[1];
                bh[nt2*2+1][0] = r[2]; bh[nt2*2+1][1] = r[3];
                LDMX4(r, sw + 49152);
                bl[nt2*2][0] = r[0]; bl[nt2*2][1] = r[1];
                bl[nt2*2+1][0] = r[2]; bl[nt2*2+1][1] = r[3];
            }
#pragma unroll
            for (int mt = 0; mt < 2; ++mt)
#pragma unroll
                for (int nt = 0; nt < 8; ++nt) {
                    MMA16816(acc[mt][nt], ah[mt], bh[nt]);
                    MMA16816(acc[mt][nt], ah[mt], bl[nt]);
                    MMA16816(acc[mt][nt], al[mt], bh[nt]);
                }
        }
    };

    fill(0, 0);
    const int NC = K / 64;
    for (int kt = 0; kt < NC; ++kt) {
        __syncthreads();
        compute(kt & 1);
        if (kt + 1 < NC) fill((kt + 1) & 1, (kt + 1) * 64);
    }

    // epilogue: D frag -> C
#pragma unroll
    for (int mt = 0; mt < 2; ++mt)
#pragma unroll
        for (int nt = 0; nt < 8; ++nt) {
            const int r0 = bm + m0w + mt * 16 + (lane >> 2);
            const int c0 = bn + n0w + nt * 8 + (lane & 3) * 2;
            float2 v0 = make_float2(acc[mt][nt][0], acc[mt][nt][1]);
            float2 v1 = make_float2(acc[mt][nt][2], acc[mt][nt][3]);
            *reinterpret_cast<float2*>(C + (size_t)r0 * N + c0)       = v0;
            *reinterpret_cast<float2*>(C + (size_t)(r0 + 8) * N + c0) = v1;
        }
}
#define GEMM_SMEM (2*GBUF)

// ------------------- Q post: RMSNorm + RoPE, split gate --------------------
__global__ __launch_bounds__(128) void postq(const float* __restrict__ cosb,
                                             const float* __restrict__ sinb,
                                             const float* __restrict__ qw) {
    const int idx = blockIdx.x;
    const int h = idx % NH;
    const int bs = idx / NH;
    const int d = threadIdx.x;
    const float* row = g_qraw + (size_t)bs * (2*OWID) + (size_t)h * (2*HD);
    float x = row[d];
    float g = row[HD + d];
    float v = x * x;
#pragma unroll
    for (int o = 16; o >= 1; o >>= 1) v += __shfl_xor_sync(0xffffffffu, v, o);
    __shared__ float red[4];
    __shared__ float buf[HD];
    if ((d & 31) == 0) red[d >> 5] = v;
    __syncthreads();
    float ss = red[0] + red[1] + red[2] + red[3];
    float r = rsqrtf(ss * (1.f / HD) + EPSF);
    float xn = x * r * qw[d];
    buf[d] = xn;
    __syncthreads();
    float other = (d < 64) ? -buf[d + 64] : buf[d - 64];
    float c = cosb[(size_t)bs * HD + d];
    float sn = sinb[(size_t)bs * HD + d];
    float q = xn * c + other * sn;
    const int b = bs >> 11, s = bs & (SLEN - 1);
    g_q[(((size_t)b * NH + h) * SLEN + s) * HD + d] = q;
    g_gate[(size_t)bs * OWID + (size_t)h * HD + d] = g;
}

// ------------------- K post: RMSNorm + RoPE in place -----------------------
__global__ __launch_bounds__(128) void postk(const float* __restrict__ cosb,
                                             const float* __restrict__ sinb,
                                             const float* __restrict__ kw) {
    const int idx = blockIdx.x;
    const int kh = idx % NKV;
    const int bs = idx / NKV;
    const int d = threadIdx.x;
    float* row = g_kraw + (size_t)bs * KVW + (size_t)kh * HD;
    float x = row[d];
    float v = x * x;
#pragma unroll
    for (int o = 16; o >= 1; o >>= 1) v += __shfl_xor_sync(0xffffffffu, v, o);
    __shared__ float red[4];
    __shared__ float buf[HD];
    if ((d & 31) == 0) red[d >> 5] = v;
    __syncthreads();
    float ss = red[0] + red[1] + red[2] + red[3];
    float r = rsqrtf(ss * (1.f / HD) + EPSF);
    float xn = x * r * kw[d];
    buf[d] = xn;
    __syncthreads();
    float other = (d < 64) ? -buf[d + 64] : buf[d - 64];
    float c = cosb[(size_t)bs * HD + d];
    float sn = sinb[(size_t)bs * HD + d];
    row[d] = xn * c + other * sn;
}

// ------------------------------ V suffix sums -------------------------------
__global__ __launch_bounds__(128) void vsuf_chunks() {
    const int blk = blockIdx.x;
    const int ch = blk % NCH;
    const int bk = blk / NCH;
    const int kh = bk % NKV, b = bk / NKV;
    const int d = threadIdx.x;
    float acc = 0.f;
    const int j0 = ch * CHS;
    for (int jj = 0; jj < CHS; ++jj)
        acc += g_vraw[(((size_t)b * SLEN + j0 + jj) * NKV + kh) * HD + d];
    g_csum[((size_t)bk * NCH + ch) * HD + d] = acc;
}

__global__ __launch_bounds__(128) void vsuf_write() {
    const int blk = blockIdx.x;
    const int ch = blk % NCH;
    const int bk = blk / NCH;
    const int kh = bk % NKV, b = bk / NKV;
    const int d = threadIdx.x;
    float acc = 0.f;
    for (int c = ch + 1; c < NCH; ++c)
        acc += g_csum[((size_t)bk * NCH + c) * HD + d];
    for (int jj = CHS - 1; jj >= 0; --jj) {
        const int j = ch * CHS + jj;
        g_vsuf[((size_t)bk * SLEN + j) * HD + d] = acc;
        acc += g_vraw[(((size_t)b * SLEN + j) * NKV + kh) * HD + d];
    }
}

// -------- pass A: scores -> attn scratch (causal tiles) + row stats ---------
__global__ __launch_bounds__(256, 1) void attn_pass_a(float* __restrict__ attn) {
    extern __shared__ float smemf[];
    float* qsm = smemf;
    float* ksm = smemf + 16384;
    const int tid = threadIdx.x, tx = tid & 15, ty = tid >> 4;
    const int qt = blockIdx.x, bh = blockIdx.y;
    const int b = bh >> 4, h = bh & 15, kh = h >> 1;
    const int qi0 = qt * 128;

    const float* qb = g_q + ((size_t)bh * SLEN + qi0) * HD;
#pragma unroll
    for (int it = 0; it < 16; ++it) {
        int slot = it * 256 + tid;
        int r = slot & 127, d4 = (slot >> 7) * 4;
        float4 v = *reinterpret_cast<const float4*>(qb + (size_t)r * HD + d4);
        qsm[(d4+0)*128+r]=v.x; qsm[(d4+1)*128+r]=v.y; qsm[(d4+2)*128+r]=v.z; qsm[(d4+3)*128+r]=v.w;
    }
    float run_m[8], run_l[8], run_mn[8];
#pragma unroll
    for (int i = 0; i < 8; ++i) { run_m[i] = -1e30f; run_l[i] = 0.f; run_mn[i] = 1e30f; }

    const float* kb = g_kraw + (size_t)b * SLEN * KVW + (size_t)kh * HD;
    for (int kt = 0; kt < SLEN/128; ++kt) {
        const int kj0 = kt * 128;
        __syncthreads();
#pragma unroll
        for (int it = 0; it < 16; ++it) {
            int slot = it * 256 + tid;
            int c = slot & 127, d4 = (slot >> 7) * 4;
            float4 v = *reinterpret_cast<const float4*>(kb + (size_t)(kj0 + c) * KVW + d4);
            ksm[(d4+0)*128+c]=v.x; ksm[(d4+1)*128+c]=v.y; ksm[(d4+2)*128+c]=v.z; ksm[(d4+3)*128+c]=v.w;
        }
        __syncthreads();
        float acc[8][8];
#pragma unroll
        for (int i = 0; i < 8; ++i)
#pragma unroll
            for (int j = 0; j < 8; ++j) acc[i][j] = 0.f;
#pragma unroll 4
        for (int k = 0; k < 128; ++k) {
            float a[8], bb[8];
            *reinterpret_cast<float4*>(&a[0])  = *reinterpret_cast<const float4*>(&qsm[k*128 + ty*8]);
            *reinterpret_cast<float4*>(&a[4])  = *reinterpret_cast<const float4*>(&qsm[k*128 + ty*8 + 4]);
            *reinterpret_cast<float4*>(&bb[0]) = *reinterpret_cast<const float4*>(&ksm[k*128 + tx*8]);
            *reinterpret_cast<float4*>(&bb[4]) = *reinterpret_cast<const float4*>(&ksm[k*128 + tx*8 + 4]);
#pragma unroll
            for (int i = 0; i < 8; ++i)
#pragma unroll
                for (int j = 0; j < 8; ++j) acc[i][j] = fmaf(a[i], bb[j], acc[i][j]);
        }
        const bool diag = (kt == qt), caus = (kt < qt);
#pragma unroll
        for (int ii = 0; ii < 8; ++ii) {
            const int i = qi0 + ty*8 + ii;
            float s[8]; float vmx = -1e30f, vmn = 1e30f;
#pragma unroll
            for (int jj = 0; jj < 8; ++jj) {
                s[jj] = acc[ii][jj] * SCALEF;
                vmn = fminf(vmn, s[jj]);
                bool val = caus || (diag && (kj0 + tx*8 + jj) <= i);
                if (val) vmx = fmaxf(vmx, s[jj]);
            }
#pragma unroll
            for (int o = 8; o >= 1; o >>= 1) {
                vmx = fmaxf(vmx, __shfl_xor_sync(0xffffffffu, vmx, o));
                vmn = fminf(vmn, __shfl_xor_sync(0xffffffffu, vmn, o));
            }
            run_mn[ii] = fminf(run_mn[ii], vmn);
            if (caus || diag) {
                float tl = 0.f;
#pragma unroll
                for (int jj = 0; jj < 8; ++jj) {
                    bool val = caus || ((kj0 + tx*8 + jj) <= i);
                    if (val) tl += __expf(s[jj] - vmx);
                }
#pragma unroll
                for (int o = 8; o >= 1; o >>= 1) tl += __shfl_xor_sync(0xffffffffu, tl, o);
                float nm = fmaxf(run_m[ii], vmx);
                run_l[ii] = run_l[ii] * __expf(run_m[ii] - nm) + tl * __expf(vmx - nm);
                run_m[ii] = nm;
                float* arow = attn + ((size_t)bh * SLEN + i) * SLEN + kj0 + tx*8;
                *reinterpret_cast<float4*>(arow)   = make_float4(s[0],s[1],s[2],s[3]);
                *reinterpret_cast<float4*>(arow+4) = make_float4(s[4],s[5],s[6],s[7]);
            }
        }
    }
    if (tx == 0) {
#pragma unroll
        for (int ii = 0; ii < 8; ++ii) {
            const int i = qi0 + ty*8 + ii;
            float m = run_m[ii];
            float e = __expf(run_mn[ii] - 20.f - m);
            float L = run_l[ii] + (float)(SLEN - 1 - i) * e;
            float id = 1.f / L;
            g_sm [(size_t)bh * SLEN + i] = m;
            g_sid[(size_t)bh * SLEN + i] = id;
            g_sc [(size_t)bh * SLEN + i] = e * id;
        }
    }
}

// -------- fill fully-masked tiles with per-row constant ---------------------
__global__ __launch_bounds__(256) void fill_masked(float* __restrict__ attn) {
    const int qt = blockIdx.x, bh = blockIdx.y;
    const int i0 = qt * 128, c0 = (qt + 1) * 128;
    const int nc4 = (SLEN - c0) >> 2;
    for (int r = 0; r < 128; ++r) {
        const int i = i0 + r;
        float c = g_sc[(size_t)bh * SLEN + i];
        float4 cv = make_float4(c, c, c, c);
        float4* row = reinterpret_cast<float4*>(attn + ((size_t)bh * SLEN + i) * SLEN + c0);
        for (int x = threadIdx.x; x < nc4; x += 256) row[x] = cv;
    }
}

// -------- pass B: finalize probs on causal tiles + PV + gate ----------------
__global__ __launch_bounds__(256, 1) void attn_pass_b(float* __restrict__ attn) {
    extern __shared__ float smemf[];
    float* ps = smemf;
    float* vs = smemf + 16384;
    const int tid = threadIdx.x, tx = tid & 15, ty = tid >> 4;
    const int qt = blockIdx.x, bh = blockIdx.y;
    const int b = bh >> 4, h = bh & 15, kh = h >> 1;
    const int qi0 = qt * 128;

    float m8[8], id8[8], c8[8];
#pragma unroll
    for (int ii = 0; ii < 8; ++ii) {
        size_t ri = (size_t)bh * SLEN + qi0 + ty*8 + ii;
        m8[ii] = g_sm[ri]; id8[ii] = g_sid[ri]; c8[ii] = g_sc[ri];
    }
    float acc[8][8];
#pragma unroll
    for (int i = 0; i < 8; ++i)
#pragma unroll
        for (int j = 0; j < 8; ++j) acc[i][j] = 0.f;

    const float* vb = g_vraw + (size_t)b * SLEN * KVW + (size_t)kh * HD;
    for (int kt = 0; kt <= qt; ++kt) {
        const int kj0 = kt * 128;
        __syncthreads();
#pragma unroll
        for (int it = 0; it < 16; ++it) {
            int slot = it * 256 + tid;
            int c = slot >> 5, d4 = (slot & 31) * 4;
            *reinterpret_cast<float4*>(&vs[c*128 + d4]) =
                *reinterpret_cast<const float4*>(vb + (size_t)(kj0 + c) * KVW + d4);
        }
        const bool diag = (kt == qt);
#pragma unroll
        for (int ii = 0; ii < 8; ++ii) {
            const int i = qi0 + ty*8 + ii;
            float* arow = attn + ((size_t)bh * SLEN + i) * SLEN + kj0 + tx*8;
            float4 s0 = *reinterpret_cast<const float4*>(arow);
            float4 s1 = *reinterpret_cast<const float4*>(arow + 4);
            float sv[8] = {s0.x, s0.y, s0.z, s0.w, s1.x, s1.y, s1.z, s1.w};
            float pw[8], pp[8];
#pragma unroll
            for (int jj = 0; jj < 8; ++jj) {
                float e = __expf(sv[jj] - m8[ii]) * id8[ii];
                bool val = !diag || ((kj0 + tx*8 + jj) <= i);
                pw[jj] = val ? e : c8[ii];
                pp[jj] = val ? e : 0.f;
            }
            *reinterpret_cast<float4*>(arow)   = make_float4(pw[0],pw[1],pw[2],pw[3]);
            *reinterpret_cast<float4*>(arow+4) = make_float4(pw[4],pw[5],pw[6],pw[7]);
            float* prow = &ps[(ty*8 + ii) * 128 + tx*8];
            *reinterpret_cast<float4*>(prow)   = make_float4(pp[0],pp[1],pp[2],pp[3]);
            *reinterpret_cast<float4*>(prow+4) = make_float4(pp[4],pp[5],pp[6],pp[7]);
        }
        __syncthreads();
#pragma unroll 4
        for (int j = 0; j < 128; ++j) {
            float a[8], bb[8];
#pragma unroll
            for (int ii = 0; ii < 8; ++ii) a[ii] = ps[(ty*8 + ii) * 128 + j];
            *reinterpret_cast<float4*>(&bb[0]) = *reinterpret_cast<const float4*>(&vs[j*128 + tx*8]);
            *reinterpret_cast<float4*>(&bb[4]) = *reinterpret_cast<const float4*>(&vs[j*128 + tx*8 + 4]);
#pragma unroll
            for (int ii = 0; ii < 8; ++ii)
#pragma unroll
                for (int dd = 0; dd < 8; ++dd) acc[ii][dd] = fmaf(a[ii], bb[dd], acc[ii][dd]);
        }
    }
#pragma unroll
    for (int ii = 0; ii < 8; ++ii) {
        const int i = qi0 + ty*8 + ii;
        const float* vsf  = g_vsuf + (((size_t)(b * NKV + kh)) * SLEN + i) * HD + tx*8;
        const float* grow = g_gate + ((size_t)b * SLEN + i) * OWID + (size_t)h * HD + tx*8;
        float*       orow = g_ao   + ((size_t)b * SLEN + i) * OWID + (size_t)h * HD + tx*8;
        float o[8];
#pragma unroll
        for (int dd = 0; dd < 8; ++dd) {
            float val = acc[ii][dd] + c8[ii] * vsf[dd];
            o[dd] = val / (1.f + __expf(-grow[dd]));
        }
        *reinterpret_cast<float4*>(orow)   = make_float4(o[0],o[1],o[2],o[3]);
        *reinterpret_cast<float4*>(orow+4) = make_float4(o[4],o[5],o[6],o[7]);
    }
}

// ----------------------------------------------------------------------------
extern "C" void kernel_launch(void* const* d_in, const int* in_sizes, int n_in,
                              void* d_out, int out_size) {
    const float* hidden = (const float*)d_in[0];
    const float* cosb   = (const float*)d_in[1];
    const float* sinb   = (const float*)d_in[2];
    const float* Wq     = (const float*)d_in[4];
    const float* Wk     = (const float*)d_in[5];
    const float* Wv     = (const float*)d_in[6];
    const float* Wo     = (const float*)d_in[7];
    const float* qnw    = (const float*)d_in[8];
    const float* knw    = (const float*)d_in[9];

    float* out_ptr  = (float*)d_out;
    float* attn_ptr = out_ptr + (size_t)NBATCH * SLEN * HDIM;

    float *p_qraw, *p_kraw, *p_vraw, *p_ao;
    cudaGetSymbolAddress((void**)&p_qraw, g_qraw);
    cudaGetSymbolAddress((void**)&p_kraw, g_kraw);
    cudaGetSymbolAddress((void**)&p_vraw, g_vraw);
    cudaGetSymbolAddress((void**)&p_ao,   g_ao);

    cudaFuncSetAttribute(gemm_tc,     cudaFuncAttributeMaxDynamicSharedMemorySize, GEMM_SMEM);
    cudaFuncSetAttribute(attn_pass_a, cudaFuncAttributeMaxDynamicSharedMemorySize, 131072);
    cudaFuncSetAttribute(attn_pass_b, cudaFuncAttributeMaxDynamicSharedMemorySize, 131072);

    // QKV projections (HMMA fp16x3)
    gemm_tc<<<dim3(2*OWID/128, TTOK/128), 256, GEMM_SMEM>>>(hidden, Wq, p_qraw, TTOK, 2*OWID, HDIM);
    gemm_tc<<<dim3(KVW/128,    TTOK/128), 256, GEMM_SMEM>>>(hidden, Wk, p_kraw, TTOK, KVW,    HDIM);
    gemm_tc<<<dim3(KVW/128,    TTOK/128), 256, GEMM_SMEM>>>(hidden, Wv, p_vraw, TTOK, KVW,    HDIM);

    // norms + rope + gate split
    postq<<<TTOK * NH,  128>>>(cosb, sinb, qnw);
    postk<<<TTOK * NKV, 128>>>(cosb, sinb, knw);

    // V suffix sums
    vsuf_chunks<<<NBATCH * NKV * NCH, 128>>>();
    vsuf_write <<<NBATCH * NKV * NCH, 128>>>();

    // attention
    attn_pass_a<<<dim3(SLEN/128, BH), 256, 131072>>>(attn_ptr);
    fill_masked<<<dim3(SLEN/128 - 1, BH), 256>>>(attn_ptr);
    attn_pass_b<<<dim3(SLEN/128, BH), 256, 131072>>>(attn_ptr);

    // output projection (HMMA fp16x3)
    gemm_tc<<<dim3(HDIM/128, TTOK/128), 256, GEMM_SMEM>>>(p_ao, Wo, out_ptr, TTOK, HDIM, OWID);
}

// round 14
// speedup vs baseline: 1.5652x; 1.0008x over previous
#include <cuda_runtime.h>
#include <cuda_fp16.h>
#include <cuda_bf16.h>
#include <cstdint>

#define NBATCH 2
#define SLEN   2048
#define HDIM   2048
#define NH     16
#define NKV    8
#define HD     128
#define TTOK   (NBATCH*SLEN)          /* 4096 */
#define BH     (NBATCH*NH)            /* 32 */
#define KVW    (NKV*HD)               /* 1024 */
#define OWID   (NH*HD)                /* 2048 */
#define SCALEF 0.08838834764831845f
#define EPSF   1e-6f
#define NCH    16
#define CHS    (SLEN/NCH)             /* 128 */

// ------------------------- device scratch (no runtime alloc) ---------------
__device__ float g_qraw[(size_t)TTOK * (2*OWID)];
__device__ float g_kraw[(size_t)TTOK * KVW];
__device__ float g_vraw[(size_t)TTOK * KVW];
__device__ float g_q   [(size_t)BH * SLEN * HD];
__device__ float g_gate[(size_t)TTOK * OWID];
__device__ float g_vsuf[(size_t)NBATCH * NKV * SLEN * HD];
__device__ float g_csum[(size_t)NBATCH * NKV * NCH * HD];
__device__ float g_sm  [(size_t)BH * SLEN];
__device__ float g_sid [(size_t)BH * SLEN];
__device__ float g_sc  [(size_t)BH * SLEN];
__device__ float g_ao  [(size_t)TTOK * OWID];

// ----------------------------- helpers -------------------------------------
__device__ __forceinline__ uint32_t smem_u32(const void* p) {
    uint32_t a;
    asm("{ .reg .u64 t; cvta.to.shared.u64 t, %1; cvt.u32.u64 %0, t; }" : "=r"(a) : "l"(p));
    return a;
}

#define LDMX4(r, a) \
    asm volatile("ldmatrix.sync.aligned.m8n8.x4.shared.b16 {%0,%1,%2,%3}, [%4];" \
        : "=r"((r)[0]), "=r"((r)[1]), "=r"((r)[2]), "=r"((r)[3]) : "r"(a))

#define MMA16816(d, a, b) \
    asm volatile("mma.sync.aligned.m16n8k16.row.col.f32.f16.f16.f32 " \
        "{%0,%1,%2,%3}, {%4,%5,%6,%7}, {%8,%9}, {%0,%1,%2,%3};" \
        : "+f"((d)[0]), "+f"((d)[1]), "+f"((d)[2]), "+f"((d)[3]) \
        : "r"((a)[0]), "r"((a)[1]), "r"((a)[2]), "r"((a)[3]), \
          "r"((b)[0]), "r"((b)[1]))

// fp32x4 -> fp16 hi/lo split (hi + lo ~ 22-bit mantissa effective)
__device__ __forceinline__ void split4h(float4 v, uint2& hi, uint2& lo) {
    __half2 h01 = __floats2half2_rn(v.x, v.y);
    __half2 h23 = __floats2half2_rn(v.z, v.w);
    float2 f01 = __half22float2(h01), f23 = __half22float2(h23);
    __half2 l01 = __floats2half2_rn(v.x - f01.x, v.y - f01.y);
    __half2 l23 = __floats2half2_rn(v.z - f23.x, v.w - f23.y);
    hi.x = *reinterpret_cast<uint32_t*>(&h01);
    hi.y = *reinterpret_cast<uint32_t*>(&h23);
    lo.x = *reinterpret_cast<uint32_t*>(&l01);
    lo.y = *reinterpret_cast<uint32_t*>(&l23);
}

// --------- HMMA GEMM: C[M,N] = A[M,K] @ W[N,K]^T, fp16x3 split -------------
// 128x128 tile/CTA, 8 warps (4M x 2N), K-chunks of 64, double-buffered SMEM.
// Per-buffer layout: Ahi @0, Alo @16K, Whi @32K, Wlo @48K (fp16, SW128).
#define GBUF 65536
__global__ __launch_bounds__(256, 1) void gemm_tc(const float* __restrict__ A,
                                                  const float* __restrict__ W,
                                                  float* __restrict__ C,
                                                  int M, int N, int K) {
    extern __shared__ __align__(1024) char smem[];
    const int tid = threadIdx.x, wid = tid >> 5, lane = tid & 31;
    const int bm = blockIdx.y * 128, bn = blockIdx.x * 128;
    const int m0w = (wid & 3) * 32, n0w = (wid >> 2) * 64;
    const uint32_t sbase = smem_u32(smem);

    float acc[2][8][4];
#pragma unroll
    for (int mt = 0; mt < 2; ++mt)
#pragma unroll
        for (int nt = 0; nt < 8; ++nt)
#pragma unroll
            for (int q = 0; q < 4; ++q) acc[mt][nt][q] = 0.f;

    auto fill = [&](int buf, int k0) {
        char* bb = smem + (size_t)buf * GBUF;
#pragma unroll
        for (int it = 0; it < 8; ++it) {
            int slot = it * 256 + tid;
            int row = slot >> 4, c4 = slot & 15;          // 16 float4 per row
            uint32_t off = (uint32_t)row * 128 + c4 * 8;  // fp16 tile byte offset
            uint32_t sw = off ^ ((off >> 3) & 0x70);
            float4 va = *reinterpret_cast<const float4*>(A + (size_t)(bm + row) * K + k0 + c4 * 4);
            uint2 h, l; split4h(va, h, l);
            *reinterpret_cast<uint2*>(bb + sw)         = h;
            *reinterpret_cast<uint2*>(bb + 16384 + sw) = l;
            float4 vw = *reinterpret_cast<const float4*>(W + (size_t)(bn + row) * K + k0 + c4 * 4);
            split4h(vw, h, l);
            *reinterpret_cast<uint2*>(bb + 32768 + sw) = h;
            *reinterpret_cast<uint2*>(bb + 49152 + sw) = l;
        }
    };

    auto compute = [&](int buf) {
        const uint32_t base = sbase + buf * GBUF;
#pragma unroll
        for (int ks = 0; ks < 4; ++ks) {
            uint32_t ah[2][4], al[2][4], bh[8][2], bl[8][2];
#pragma unroll
            for (int mt = 0; mt < 2; ++mt) {
                uint32_t off = (uint32_t)(m0w + mt * 16 + (lane & 15)) * 128
                             + ((lane >> 4) << 4) + ks * 32;
                uint32_t sw = base + (off ^ ((off >> 3) & 0x70));
                LDMX4(ah[mt], sw);
                LDMX4(al[mt], sw + 16384);
            }
#pragma unroll
            for (int nt2 = 0; nt2 < 4; ++nt2) {
                uint32_t off = (uint32_t)(n0w + nt2 * 16 + (lane & 7) + ((lane >> 4) << 3)) * 128
                             + (((lane >> 3) & 1) << 4) + ks * 32;
                uint32_t sw = base + (off ^ ((off >> 3) & 0x70));
                uint32_t r[4];
                LDMX4(r, sw + 32768);
                bh[nt2*2][0] = r[0]; bh[nt2*2][1] = r[1];
                bh[nt2*2+1][0] = r[2]; bh[nt2*2+1][1] = r[3];
                LDMX4(r, sw + 49152);
                bl[nt2*2][0] = r[0]; bl[nt2*2][1] = r[1];
                bl[nt2*2+1][0] = r[2]; bl[nt2*2+1][1] = r[3];
            }
#pragma unroll
            for (int mt = 0; mt < 2; ++mt)
#pragma unroll
                for (int nt = 0; nt < 8; ++nt) {
                    MMA16816(acc[mt][nt], ah[mt], bh[nt]);
                    MMA16816(acc[mt][nt], ah[mt], bl[nt]);
                    MMA16816(acc[mt][nt], al[mt], bh[nt]);
                }
        }
    };

    fill(0, 0);
    const int NC = K / 64;
    for (int kt = 0; kt < NC; ++kt) {
        __syncthreads();
        compute(kt & 1);
        if (kt + 1 < NC) fill((kt + 1) & 1, (kt + 1) * 64);
    }

    // epilogue: D frag -> C
#pragma unroll
    for (int mt = 0; mt < 2; ++mt)
#pragma unroll
        for (int nt = 0; nt < 8; ++nt) {
            const int r0 = bm + m0w + mt * 16 + (lane >> 2);
            const int c0 = bn + n0w + nt * 8 + (lane & 3) * 2;
            float2 v0 = make_float2(acc[mt][nt][0], acc[mt][nt][1]);
            float2 v1 = make_float2(acc[mt][nt][2], acc[mt][nt][3]);
            *reinterpret_cast<float2*>(C + (size_t)r0 * N + c0)       = v0;
            *reinterpret_cast<float2*>(C + (size_t)(r0 + 8) * N + c0) = v1;
        }
}
#define GEMM_SMEM (2*GBUF)

// ------------------- Q post: RMSNorm + RoPE, split gate --------------------
__global__ __launch_bounds__(128) void postq(const float* __restrict__ cosb,
                                             const float* __restrict__ sinb,
                                             const float* __restrict__ qw) {
    const int idx = blockIdx.x;
    const int h = idx % NH;
    const int bs = idx / NH;
    const int d = threadIdx.x;
    const float* row = g_qraw + (size_t)bs * (2*OWID) + (size_t)h * (2*HD);
    float x = row[d];
    float g = row[HD + d];
    float v = x * x;
#pragma unroll
    for (int o = 16; o >= 1; o >>= 1) v += __shfl_xor_sync(0xffffffffu, v, o);
    __shared__ float red[4];
    __shared__ float buf[HD];
    if ((d & 31) == 0) red[d >> 5] = v;
    __syncthreads();
    float ss = red[0] + red[1] + red[2] + red[3];
    float r = rsqrtf(ss * (1.f / HD) + EPSF);
    float xn = x * r * qw[d];
    buf[d] = xn;
    __syncthreads();
    float other = (d < 64) ? -buf[d + 64] : buf[d - 64];
    float c = cosb[(size_t)bs * HD + d];
    float sn = sinb[(size_t)bs * HD + d];
    float q = xn * c + other * sn;
    const int b = bs >> 11, s = bs & (SLEN - 1);
    g_q[(((size_t)b * NH + h) * SLEN + s) * HD + d] = q;
    g_gate[(size_t)bs * OWID + (size_t)h * HD + d] = g;
}

// ------------------- K post: RMSNorm + RoPE in place -----------------------
__global__ __launch_bounds__(128) void postk(const float* __restrict__ cosb,
                                             const float* __restrict__ sinb,
                                             const float* __restrict__ kw) {
    const int idx = blockIdx.x;
    const int kh = idx % NKV;
    const int bs = idx / NKV;
    const int d = threadIdx.x;
    float* row = g_kraw + (size_t)bs * KVW + (size_t)kh * HD;
    float x = row[d];
    float v = x * x;
#pragma unroll
    for (int o = 16; o >= 1; o >>= 1) v += __shfl_xor_sync(0xffffffffu, v, o);
    __shared__ float red[4];
    __shared__ float buf[HD];
    if ((d & 31) == 0) red[d >> 5] = v;
    __syncthreads();
    float ss = red[0] + red[1] + red[2] + red[3];
    float r = rsqrtf(ss * (1.f / HD) + EPSF);
    float xn = x * r * kw[d];
    buf[d] = xn;
    __syncthreads();
    float other = (d < 64) ? -buf[d + 64] : buf[d - 64];
    float c = cosb[(size_t)bs * HD + d];
    float sn = sinb[(size_t)bs * HD + d];
    row[d] = xn * c + other * sn;
}

// ------------------------------ V suffix sums -------------------------------
__global__ __launch_bounds__(128) void vsuf_chunks() {
    const int blk = blockIdx.x;
    const int ch = blk % NCH;
    const int bk = blk / NCH;
    const int kh = bk % NKV, b = bk / NKV;
    const int d = threadIdx.x;
    float acc = 0.f;
    const int j0 = ch * CHS;
    for (int jj = 0; jj < CHS; ++jj)
        acc += g_vraw[(((size_t)b * SLEN + j0 + jj) * NKV + kh) * HD + d];
    g_csum[((size_t)bk * NCH + ch) * HD + d] = acc;
}

__global__ __launch_bounds__(128) void vsuf_write() {
    const int blk = blockIdx.x;
    const int ch = blk % NCH;
    const int bk = blk / NCH;
    const int kh = bk % NKV, b = bk / NKV;
    const int d = threadIdx.x;
    float acc = 0.f;
    for (int c = ch + 1; c < NCH; ++c)
        acc += g_csum[((size_t)bk * NCH + c) * HD + d];
    for (int jj = CHS - 1; jj >= 0; --jj) {
        const int j = ch * CHS + jj;
        g_vsuf[((size_t)bk * SLEN + j) * HD + d] = acc;
        acc += g_vraw[(((size_t)b * SLEN + j) * NKV + kh) * HD + d];
    }
}

// -------- pass A: scores -> attn scratch (causal tiles) + row stats ---------
__global__ __launch_bounds__(256, 1) void attn_pass_a(float* __restrict__ attn) {
    extern __shared__ float smemf[];
    float* qsm = smemf;
    float* ksm = smemf + 16384;
    const int tid = threadIdx.x, tx = tid & 15, ty = tid >> 4;
    const int qt = blockIdx.x, bh = blockIdx.y;
    const int b = bh >> 4, h = bh & 15, kh = h >> 1;
    const int qi0 = qt * 128;

    const float* qb = g_q + ((size_t)bh * SLEN + qi0) * HD;
#pragma unroll
    for (int it = 0; it < 16; ++it) {
        int slot = it * 256 + tid;
        int r = slot & 127, d4 = (slot >> 7) * 4;
        float4 v = *reinterpret_cast<const float4*>(qb + (size_t)r * HD + d4);
        qsm[(d4+0)*128+r]=v.x; qsm[(d4+1)*128+r]=v.y; qsm[(d4+2)*128+r]=v.z; qsm[(d4+3)*128+r]=v.w;
    }
    float run_m[8], run_l[8], run_mn[8];
#pragma unroll
    for (int i = 0; i < 8; ++i) { run_m[i] = -1e30f; run_l[i] = 0.f; run_mn[i] = 1e30f; }

    const float* kb = g_kraw + (size_t)b * SLEN * KVW + (size_t)kh * HD;
    for (int kt = 0; kt < SLEN/128; ++kt) {
        const int kj0 = kt * 128;
        __syncthreads();
#pragma unroll
        for (int it = 0; it < 16; ++it) {
            int slot = it * 256 + tid;
            int c = slot & 127, d4 = (slot >> 7) * 4;
            float4 v = *reinterpret_cast<const float4*>(kb + (size_t)(kj0 + c) * KVW + d4);
            ksm[(d4+0)*128+c]=v.x; ksm[(d4+1)*128+c]=v.y; ksm[(d4+2)*128+c]=v.z; ksm[(d4+3)*128+c]=v.w;
        }
        __syncthreads();
        float acc[8][8];
#pragma unroll
        for (int i = 0; i < 8; ++i)
#pragma unroll
            for (int j = 0; j < 8; ++j) acc[i][j] = 0.f;
#pragma unroll 4
        for (int k = 0; k < 128; ++k) {
            float a[8], bb[8];
            *reinterpret_cast<float4*>(&a[0])  = *reinterpret_cast<const float4*>(&qsm[k*128 + ty*8]);
            *reinterpret_cast<float4*>(&a[4])  = *reinterpret_cast<const float4*>(&qsm[k*128 + ty*8 + 4]);
            *reinterpret_cast<float4*>(&bb[0]) = *reinterpret_cast<const float4*>(&ksm[k*128 + tx*8]);
            *reinterpret_cast<float4*>(&bb[4]) = *reinterpret_cast<const float4*>(&ksm[k*128 + tx*8 + 4]);
#pragma unroll
            for (int i = 0; i < 8; ++i)
#pragma unroll
                for (int j = 0; j < 8; ++j) acc[i][j] = fmaf(a[i], bb[j], acc[i][j]);
        }
        const bool diag = (kt == qt), caus = (kt < qt);
#pragma unroll
        for (int ii = 0; ii < 8; ++ii) {
            const int i = qi0 + ty*8 + ii;
            float s[8]; float vmx = -1e30f, vmn = 1e30f;
#pragma unroll
            for (int jj = 0; jj < 8; ++jj) {
                s[jj] = acc[ii][jj] * SCALEF;
                vmn = fminf(vmn, s[jj]);
                bool val = caus || (diag && (kj0 + tx*8 + jj) <= i);
                if (val) vmx = fmaxf(vmx, s[jj]);
            }
#pragma unroll
            for (int o = 8; o >= 1; o >>= 1) {
                vmx = fmaxf(vmx, __shfl_xor_sync(0xffffffffu, vmx, o));
                vmn = fminf(vmn, __shfl_xor_sync(0xffffffffu, vmn, o));
            }
            run_mn[ii] = fminf(run_mn[ii], vmn);
            if (caus || diag) {
                float tl = 0.f;
#pragma unroll
                for (int jj = 0; jj < 8; ++jj) {
                    bool val = caus || ((kj0 + tx*8 + jj) <= i);
                    if (val) tl += __expf(s[jj] - vmx);
                }
#pragma unroll
                for (int o = 8; o >= 1; o >>= 1) tl += __shfl_xor_sync(0xffffffffu, tl, o);
                float nm = fmaxf(run_m[ii], vmx);
                run_l[ii] = run_l[ii] * __expf(run_m[ii] - nm) + tl * __expf(vmx - nm);
                run_m[ii] = nm;
                float* arow = attn + ((size_t)bh * SLEN + i) * SLEN + kj0 + tx*8;
                *reinterpret_cast<float4*>(arow)   = make_float4(s[0],s[1],s[2],s[3]);
                *reinterpret_cast<float4*>(arow+4) = make_float4(s[4],s[5],s[6],s[7]);
            }
        }
    }
    if (tx == 0) {
#pragma unroll
        for (int ii = 0; ii < 8; ++ii) {
            const int i = qi0 + ty*8 + ii;
            float m = run_m[ii];
            float e = __expf(run_mn[ii] - 20.f - m);
            float L = run_l[ii] + (float)(SLEN - 1 - i) * e;
            float id = 1.f / L;
            g_sm [(size_t)bh * SLEN + i] = m;
            g_sid[(size_t)bh * SLEN + i] = id;
            g_sc [(size_t)bh * SLEN + i] = e * id;
        }
    }
}

// -------- fill fully-masked tiles with per-row constant ---------------------
__global__ __launch_bounds__(256) void fill_masked(float* __restrict__ attn) {
    const int qt = blockIdx.x, bh = blockIdx.y;
    const int i0 = qt * 128, c0 = (qt + 1) * 128;
    const int nc4 = (SLEN - c0) >> 2;
    for (int r = 0; r < 128; ++r) {
        const int i = i0 + r;
        float c = g_sc[(size_t)bh * SLEN + i];
        float4 cv = make_float4(c, c, c, c);
        float4* row = reinterpret_cast<float4*>(attn + ((size_t)bh * SLEN + i) * SLEN + c0);
        for (int x = threadIdx.x; x < nc4; x += 256) row[x] = cv;
    }
}

// -------- pass B: finalize probs on causal tiles + PV + gate ----------------
__global__ __launch_bounds__(256, 1) void attn_pass_b(float* __restrict__ attn) {
    extern __shared__ float smemf[];
    float* ps = smemf;
    float* vs = smemf + 16384;
    const int tid = threadIdx.x, tx = tid & 15, ty = tid >> 4;
    const int qt = blockIdx.x, bh = blockIdx.y;
    const int b = bh >> 4, h = bh & 15, kh = h >> 1;
    const int qi0 = qt * 128;

    float m8[8], id8[8], c8[8];
#pragma unroll
    for (int ii = 0; ii < 8; ++ii) {
        size_t ri = (size_t)bh * SLEN + qi0 + ty*8 + ii;
        m8[ii] = g_sm[ri]; id8[ii] = g_sid[ri]; c8[ii] = g_sc[ri];
    }
    float acc[8][8];
#pragma unroll
    for (int i = 0; i < 8; ++i)
#pragma unroll
        for (int j = 0; j < 8; ++j) acc[i][j] = 0.f;

    const float* vb = g_vraw + (size_t)b * SLEN * KVW + (size_t)kh * HD;
    for (int kt = 0; kt <= qt; ++kt) {
        const int kj0 = kt * 128;
        __syncthreads();
#pragma unroll
        for (int it = 0; it < 16; ++it) {
            int slot = it * 256 + tid;
            int c = slot >> 5, d4 = (slot & 31) * 4;
            *reinterpret_cast<float4*>(&vs[c*128 + d4]) =
                *reinterpret_cast<const float4*>(vb + (size_t)(kj0 + c) * KVW + d4);
        }
        const bool diag = (kt == qt);
#pragma unroll
        for (int ii = 0; ii < 8; ++ii) {
            const int i = qi0 + ty*8 + ii;
            float* arow = attn + ((size_t)bh * SLEN + i) * SLEN + kj0 + tx*8;
            float4 s0 = *reinterpret_cast<const float4*>(arow);
            float4 s1 = *reinterpret_cast<const float4*>(arow + 4);
            float sv[8] = {s0.x, s0.y, s0.z, s0.w, s1.x, s1.y, s1.z, s1.w};
            float pw[8], pp[8];
#pragma unroll
            for (int jj = 0; jj < 8; ++jj) {
                float e = __expf(sv[jj] - m8[ii]) * id8[ii];
                bool val = !diag || ((kj0 + tx*8 + jj) <= i);
                pw[jj] = val ? e : c8[ii];
                pp[jj] = val ? e : 0.f;
            }
            *reinterpret_cast<float4*>(arow)   = make_float4(pw[0],pw[1],pw[2],pw[3]);
            *reinterpret_cast<float4*>(arow+4) = make_float4(pw[4],pw[5],pw[6],pw[7]);
            float* prow = &ps[(ty*8 + ii) * 128 + tx*8];
            *reinterpret_cast<float4*>(prow)   = make_float4(pp[0],pp[1],pp[2],pp[3]);
            *reinterpret_cast<float4*>(prow+4) = make_float4(pp[4],pp[5],pp[6],pp[7]);
        }
        __syncthreads();
#pragma unroll 4
        for (int j = 0; j < 128; ++j) {
            float a[8], bb[8];
#pragma unroll
            for (int ii = 0; ii < 8; ++ii) a[ii] = ps[(ty*8 + ii) * 128 + j];
            *reinterpret_cast<float4*>(&bb[0]) = *reinterpret_cast<const float4*>(&vs[j*128 + tx*8]);
            *reinterpret_cast<float4*>(&bb[4]) = *reinterpret_cast<const float4*>(&vs[j*128 + tx*8 + 4]);
#pragma unroll
            for (int ii = 0; ii < 8; ++ii)
#pragma unroll
                for (int dd = 0; dd < 8; ++dd) acc[ii][dd] = fmaf(a[ii], bb[dd], acc[ii][dd]);
        }
    }
#pragma unroll
    for (int ii = 0; ii < 8; ++ii) {
        const int i = qi0 + ty*8 + ii;
        const float* vsf  = g_vsuf + (((size_t)(b * NKV + kh)) * SLEN + i) * HD + tx*8;
        const float* grow = g_gate + ((size_t)b * SLEN + i) * OWID + (size_t)h * HD + tx*8;
        float*       orow = g_ao   + ((size_t)b * SLEN + i) * OWID + (size_t)h * HD + tx*8;
        float o[8];
#pragma unroll
        for (int dd = 0; dd < 8; ++dd) {
            float val = acc[ii][dd] + c8[ii] * vsf[dd];
            o[dd] = val / (1.f + __expf(-grow[dd]));
        }
        *reinterpret_cast<float4*>(orow)   = make_float4(o[0],o[1],o[2],o[3]);
        *reinterpret_cast<float4*>(orow+4) = make_float4(o[4],o[5],o[6],o[7]);
    }
}

// ----------------------------------------------------------------------------
extern "C" void kernel_launch(void* const* d_in, const int* in_sizes, int n_in,
                              void* d_out, int out_size) {
    const float* hidden = (const float*)d_in[0];
    const float* cosb   = (const float*)d_in[1];
    const float* sinb   = (const float*)d_in[2];
    const float* Wq     = (const float*)d_in[4];
    const float* Wk     = (const float*)d_in[5];
    const float* Wv     = (const float*)d_in[6];
    const float* Wo     = (const float*)d_in[7];
    const float* qnw    = (const float*)d_in[8];
    const float* knw    = (const float*)d_in[9];

    float* out_ptr  = (float*)d_out;
    float* attn_ptr = out_ptr + (size_t)NBATCH * SLEN * HDIM;

    float *p_qraw, *p_kraw, *p_vraw, *p_ao;
    cudaGetSymbolAddress((void**)&p_qraw, g_qraw);
    cudaGetSymbolAddress((void**)&p_kraw, g_kraw);
    cudaGetSymbolAddress((void**)&p_vraw, g_vraw);
    cudaGetSymbolAddress((void**)&p_ao,   g_ao);

    cudaFuncSetAttribute(gemm_tc,     cudaFuncAttributeMaxDynamicSharedMemorySize, GEMM_SMEM);
    cudaFuncSetAttribute(attn_pass_a, cudaFuncAttributeMaxDynamicSharedMemorySize, 131072);
    cudaFuncSetAttribute(attn_pass_b, cudaFuncAttributeMaxDynamicSharedMemorySize, 131072);

    // QKV projections (HMMA fp16x3)
    gemm_tc<<<dim3(2*OWID/128, TTOK/128), 256, GEMM_SMEM>>>(hidden, Wq, p_qraw, TTOK, 2*OWID, HDIM);
    gemm_tc<<<dim3(KVW/128,    TTOK/128), 256, GEMM_SMEM>>>(hidden, Wk, p_kraw, TTOK, KVW,    HDIM);
    gemm_tc<<<dim3(KVW/128,    TTOK/128), 256, GEMM_SMEM>>>(hidden, Wv, p_vraw, TTOK, KVW,    HDIM);

    // norms + rope + gate split
    postq<<<TTOK * NH,  128>>>(cosb, sinb, qnw);
    postk<<<TTOK * NKV, 128>>>(cosb, sinb, knw);

    // V suffix sums
    vsuf_chunks<<<NBATCH * NKV * NCH, 128>>>();
    vsuf_write <<<NBATCH * NKV * NCH, 128>>>();

    // attention
    attn_pass_a<<<dim3(SLEN/128, BH), 256, 131072>>>(attn_ptr);
    fill_masked<<<dim3(SLEN/128 - 1, BH), 256>>>(attn_ptr);
    attn_pass_b<<<dim3(SLEN/128, BH), 256, 131072>>>(attn_ptr);

    // output projection (HMMA fp16x3)
    gemm_tc<<<dim3(HDIM/128, TTOK/128), 256, GEMM_SMEM>>>(p_ao, Wo, out_ptr, TTOK, HDIM, OWID);
}

// round 15
// speedup vs baseline: 1.5667x; 1.0009x over previous
#include <cuda_runtime.h>
#include <cuda_fp16.h>
#include <cuda_bf16.h>
#include <cstdint>

#define NBATCH 2
#define SLEN   2048
#define HDIM   2048
#define NH     16
#define NKV    8
#define HD     128
#define TTOK   (NBATCH*SLEN)          /* 4096 */
#define BH     (NBATCH*NH)            /* 32 */
#define KVW    (NKV*HD)               /* 1024 */
#define OWID   (NH*HD)                /* 2048 */
#define SCALEF 0.08838834764831845f
#define EPSF   1e-6f
#define NCH    16
#define CHS    (SLEN/NCH)             /* 128 */

// ------------------------- device scratch (no runtime alloc) ---------------
__device__ float g_qraw[(size_t)TTOK * (2*OWID)];
__device__ float g_kraw[(size_t)TTOK * KVW];
__device__ float g_vraw[(size_t)TTOK * KVW];
__device__ float g_q   [(size_t)BH * SLEN * HD];
__device__ float g_gate[(size_t)TTOK * OWID];
__device__ float g_vsuf[(size_t)NBATCH * NKV * SLEN * HD];
__device__ float g_csum[(size_t)NBATCH * NKV * NCH * HD];
__device__ float g_sm  [(size_t)BH * SLEN];
__device__ float g_sid [(size_t)BH * SLEN];
__device__ float g_sc  [(size_t)BH * SLEN];
__device__ float g_ao  [(size_t)TTOK * OWID];

// ----------------------------- helpers -------------------------------------
__device__ __forceinline__ uint32_t smem_u32(const void* p) {
    uint32_t a;
    asm("{ .reg .u64 t; cvta.to.shared.u64 t, %1; cvt.u32.u64 %0, t; }" : "=r"(a) : "l"(p));
    return a;
}

#define LDMX4(r, a) \
    asm volatile("ldmatrix.sync.aligned.m8n8.x4.shared.b16 {%0,%1,%2,%3}, [%4];" \
        : "=r"((r)[0]), "=r"((r)[1]), "=r"((r)[2]), "=r"((r)[3]) : "r"(a))

#define MMA16816(d, a, b) \
    asm volatile("mma.sync.aligned.m16n8k16.row.col.f32.f16.f16.f32 " \
        "{%0,%1,%2,%3}, {%4,%5,%6,%7}, {%8,%9}, {%0,%1,%2,%3};" \
        : "+f"((d)[0]), "+f"((d)[1]), "+f"((d)[2]), "+f"((d)[3]) \
        : "r"((a)[0]), "r"((a)[1]), "r"((a)[2]), "r"((a)[3]), \
          "r"((b)[0]), "r"((b)[1]))

// fp32x4 -> fp16 hi/lo split (hi + lo ~ 22-bit mantissa effective)
__device__ __forceinline__ void split4h(float4 v, uint2& hi, uint2& lo) {
    __half2 h01 = __floats2half2_rn(v.x, v.y);
    __half2 h23 = __floats2half2_rn(v.z, v.w);
    float2 f01 = __half22float2(h01), f23 = __half22float2(h23);
    __half2 l01 = __floats2half2_rn(v.x - f01.x, v.y - f01.y);
    __half2 l23 = __floats2half2_rn(v.z - f23.x, v.w - f23.y);
    hi.x = *reinterpret_cast<uint32_t*>(&h01);
    hi.y = *reinterpret_cast<uint32_t*>(&h23);
    lo.x = *reinterpret_cast<uint32_t*>(&l01);
    lo.y = *reinterpret_cast<uint32_t*>(&l23);
}

// --------- HMMA GEMM: C[M,N] = A[M,K] @ W[N,K]^T, fp16x3 split -------------
// 128x128 tile/CTA, 8 warps (4M x 2N), K-chunks of 64, double-buffered SMEM.
// Per-buffer layout: Ahi @0, Alo @16K, Whi @32K, Wlo @48K (fp16, SW128).
#define GBUF 65536
__global__ __launch_bounds__(256, 1) void gemm_tc(const float* __restrict__ A,
                                                  const float* __restrict__ W,
                                                  float* __restrict__ C,
                                                  int M, int N, int K) {
    extern __shared__ __align__(1024) char smem[];
    const int tid = threadIdx.x, wid = tid >> 5, lane = tid & 31;
    const int bm = blockIdx.y * 128, bn = blockIdx.x * 128;
    const int m0w = (wid & 3) * 32, n0w = (wid >> 2) * 64;
    const uint32_t sbase = smem_u32(smem);

    float acc[2][8][4];
#pragma unroll
    for (int mt = 0; mt < 2; ++mt)
#pragma unroll
        for (int nt = 0; nt < 8; ++nt)
#pragma unroll
            for (int q = 0; q < 4; ++q) acc[mt][nt][q] = 0.f;

    auto fill = [&](int buf, int k0) {
        char* bb = smem + (size_t)buf * GBUF;
#pragma unroll
        for (int it = 0; it < 8; ++it) {
            int slot = it * 256 + tid;
            int row = slot >> 4, c4 = slot & 15;          // 16 float4 per row
            uint32_t off = (uint32_t)row * 128 + c4 * 8;  // fp16 tile byte offset
            uint32_t sw = off ^ ((off >> 3) & 0x70);
            float4 va = *reinterpret_cast<const float4*>(A + (size_t)(bm + row) * K + k0 + c4 * 4);
            uint2 h, l; split4h(va, h, l);
            *reinterpret_cast<uint2*>(bb + sw)         = h;
            *reinterpret_cast<uint2*>(bb + 16384 + sw) = l;
            float4 vw = *reinterpret_cast<const float4*>(W + (size_t)(bn + row) * K + k0 + c4 * 4);
            split4h(vw, h, l);
            *reinterpret_cast<uint2*>(bb + 32768 + sw) = h;
            *reinterpret_cast<uint2*>(bb + 49152 + sw) = l;
        }
    };

    auto compute = [&](int buf) {
        const uint32_t base = sbase + buf * GBUF;
#pragma unroll
        for (int ks = 0; ks < 4; ++ks) {
            uint32_t ah[2][4], al[2][4], bh[8][2], bl[8][2];
#pragma unroll
            for (int mt = 0; mt < 2; ++mt) {
                uint32_t off = (uint32_t)(m0w + mt * 16 + (lane & 15)) * 128
                             + ((lane >> 4) << 4) + ks * 32;
                uint32_t sw = base + (off ^ ((off >> 3) & 0x70));
                LDMX4(ah[mt], sw);
                LDMX4(al[mt], sw + 16384);
            }
#pragma unroll
            for (int nt2 = 0; nt2 < 4; ++nt2) {
                uint32_t off = (uint32_t)(n0w + nt2 * 16 + (lane & 7) + ((lane >> 4) << 3)) * 128
                             + (((lane >> 3) & 1) << 4) + ks * 32;
                uint32_t sw = base + (off ^ ((off >> 3) & 0x70));
                uint32_t r[4];
                LDMX4(r, sw + 32768);
                bh[nt2*2][0] = r[0]; bh[nt2*2][1] = r[1];
                bh[nt2*2+1][0] = r[2]; bh[nt2*2+1][1] = r[3];
                LDMX4(r, sw + 49152);
                bl[nt2*2][0] = r[0]; bl[nt2*2][1] = r[1];
                bl[nt2*2+1][0] = r[2]; bl[nt2*2+1][1] = r[3];
            }
#pragma unroll
            for (int mt = 0; mt < 2; ++mt)
#pragma unroll
                for (int nt = 0; nt < 8; ++nt) {
                    MMA16816(acc[mt][nt], ah[mt], bh[nt]);
                    MMA16816(acc[mt][nt], ah[mt], bl[nt]);
                    MMA16816(acc[mt][nt], al[mt], bh[nt]);
                }
        }
    };

    fill(0, 0);
    const int NC = K / 64;
    for (int kt = 0; kt < NC; ++kt) {
        __syncthreads();
        compute(kt & 1);
        if (kt + 1 < NC) fill((kt + 1) & 1, (kt + 1) * 64);
    }

    // epilogue: D frag -> C
#pragma unroll
    for (int mt = 0; mt < 2; ++mt)
#pragma unroll
        for (int nt = 0; nt < 8; ++nt) {
            const int r0 = bm + m0w + mt * 16 + (lane >> 2);
            const int c0 = bn + n0w + nt * 8 + (lane & 3) * 2;
            float2 v0 = make_float2(acc[mt][nt][0], acc[mt][nt][1]);
            float2 v1 = make_float2(acc[mt][nt][2], acc[mt][nt][3]);
            *reinterpret_cast<float2*>(C + (size_t)r0 * N + c0)       = v0;
            *reinterpret_cast<float2*>(C + (size_t)(r0 + 8) * N + c0) = v1;
        }
}
#define GEMM_SMEM (2*GBUF)

// ------------------- Q post: RMSNorm + RoPE, split gate --------------------
__global__ __launch_bounds__(128) void postq(const float* __restrict__ cosb,
                                             const float* __restrict__ sinb,
                                             const float* __restrict__ qw) {
    const int idx = blockIdx.x;
    const int h = idx % NH;
    const int bs = idx / NH;
    const int d = threadIdx.x;
    const float* row = g_qraw + (size_t)bs * (2*OWID) + (size_t)h * (2*HD);
    float x = row[d];
    float g = row[HD + d];
    float v = x * x;
#pragma unroll
    for (int o = 16; o >= 1; o >>= 1) v += __shfl_xor_sync(0xffffffffu, v, o);
    __shared__ float red[4];
    __shared__ float buf[HD];
    if ((d & 31) == 0) red[d >> 5] = v;
    __syncthreads();
    float ss = red[0] + red[1] + red[2] + red[3];
    float r = rsqrtf(ss * (1.f / HD) + EPSF);
    float xn = x * r * qw[d];
    buf[d] = xn;
    __syncthreads();
    float other = (d < 64) ? -buf[d + 64] : buf[d - 64];
    float c = cosb[(size_t)bs * HD + d];
    float sn = sinb[(size_t)bs * HD + d];
    float q = xn * c + other * sn;
    const int b = bs >> 11, s = bs & (SLEN - 1);
    g_q[(((size_t)b * NH + h) * SLEN + s) * HD + d] = q;
    g_gate[(size_t)bs * OWID + (size_t)h * HD + d] = g;
}

// ------------------- K post: RMSNorm + RoPE in place -----------------------
__global__ __launch_bounds__(128) void postk(const float* __restrict__ cosb,
                                             const float* __restrict__ sinb,
                                             const float* __restrict__ kw) {
    const int idx = blockIdx.x;
    const int kh = idx % NKV;
    const int bs = idx / NKV;
    const int d = threadIdx.x;
    float* row = g_kraw + (size_t)bs * KVW + (size_t)kh * HD;
    float x = row[d];
    float v = x * x;
#pragma unroll
    for (int o = 16; o >= 1; o >>= 1) v += __shfl_xor_sync(0xffffffffu, v, o);
    __shared__ float red[4];
    __shared__ float buf[HD];
    if ((d & 31) == 0) red[d >> 5] = v;
    __syncthreads();
    float ss = red[0] + red[1] + red[2] + red[3];
    float r = rsqrtf(ss * (1.f / HD) + EPSF);
    float xn = x * r * kw[d];
    buf[d] = xn;
    __syncthreads();
    float other = (d < 64) ? -buf[d + 64] : buf[d - 64];
    float c = cosb[(size_t)bs * HD + d];
    float sn = sinb[(size_t)bs * HD + d];
    row[d] = xn * c + other * sn;
}

// ------------------------------ V suffix sums -------------------------------
__global__ __launch_bounds__(128) void vsuf_chunks() {
    const int blk = blockIdx.x;
    const int ch = blk % NCH;
    const int bk = blk / NCH;
    const int kh = bk % NKV, b = bk / NKV;
    const int d = threadIdx.x;
    float acc = 0.f;
    const int j0 = ch * CHS;
    for (int jj = 0; jj < CHS; ++jj)
        acc += g_vraw[(((size_t)b * SLEN + j0 + jj) * NKV + kh) * HD + d];
    g_csum[((size_t)bk * NCH + ch) * HD + d] = acc;
}

__global__ __launch_bounds__(128) void vsuf_write() {
    const int blk = blockIdx.x;
    const int ch = blk % NCH;
    const int bk = blk / NCH;
    const int kh = bk % NKV, b = bk / NKV;
    const int d = threadIdx.x;
    float acc = 0.f;
    for (int c = ch + 1; c < NCH; ++c)
        acc += g_csum[((size_t)bk * NCH + c) * HD + d];
    for (int jj = CHS - 1; jj >= 0; --jj) {
        const int j = ch * CHS + jj;
        g_vsuf[((size_t)bk * SLEN + j) * HD + d] = acc;
        acc += g_vraw[(((size_t)b * SLEN + j) * NKV + kh) * HD + d];
    }
}

// -------- pass A: scores -> attn scratch (causal tiles) + row stats ---------
__global__ __launch_bounds__(256, 1) void attn_pass_a(float* __restrict__ attn) {
    extern __shared__ float smemf[];
    float* qsm = smemf;
    float* ksm = smemf + 16384;
    const int tid = threadIdx.x, tx = tid & 15, ty = tid >> 4;
    const int qt = blockIdx.x, bh = blockIdx.y;
    const int b = bh >> 4, h = bh & 15, kh = h >> 1;
    const int qi0 = qt * 128;

    const float* qb = g_q + ((size_t)bh * SLEN + qi0) * HD;
#pragma unroll
    for (int it = 0; it < 16; ++it) {
        int slot = it * 256 + tid;
        int r = slot & 127, d4 = (slot >> 7) * 4;
        float4 v = *reinterpret_cast<const float4*>(qb + (size_t)r * HD + d4);
        qsm[(d4+0)*128+r]=v.x; qsm[(d4+1)*128+r]=v.y; qsm[(d4+2)*128+r]=v.z; qsm[(d4+3)*128+r]=v.w;
    }
    float run_m[8], run_l[8], run_mn[8];
#pragma unroll
    for (int i = 0; i < 8; ++i) { run_m[i] = -1e30f; run_l[i] = 0.f; run_mn[i] = 1e30f; }

    const float* kb = g_kraw + (size_t)b * SLEN * KVW + (size_t)kh * HD;
    for (int kt = 0; kt < SLEN/128; ++kt) {
        const int kj0 = kt * 128;
        __syncthreads();
#pragma unroll
        for (int it = 0; it < 16; ++it) {
            int slot = it * 256 + tid;
            int c = slot & 127, d4 = (slot >> 7) * 4;
            float4 v = *reinterpret_cast<const float4*>(kb + (size_t)(kj0 + c) * KVW + d4);
            ksm[(d4+0)*128+c]=v.x; ksm[(d4+1)*128+c]=v.y; ksm[(d4+2)*128+c]=v.z; ksm[(d4+3)*128+c]=v.w;
        }
        __syncthreads();
        float acc[8][8];
#pragma unroll
        for (int i = 0; i < 8; ++i)
#pragma unroll
            for (int j = 0; j < 8; ++j) acc[i][j] = 0.f;
#pragma unroll 4
        for (int k = 0; k < 128; ++k) {
            float a[8], bb[8];
            *reinterpret_cast<float4*>(&a[0])  = *reinterpret_cast<const float4*>(&qsm[k*128 + ty*8]);
            *reinterpret_cast<float4*>(&a[4])  = *reinterpret_cast<const float4*>(&qsm[k*128 + ty*8 + 4]);
            *reinterpret_cast<float4*>(&bb[0]) = *reinterpret_cast<const float4*>(&ksm[k*128 + tx*8]);
            *reinterpret_cast<float4*>(&bb[4]) = *reinterpret_cast<const float4*>(&ksm[k*128 + tx*8 + 4]);
#pragma unroll
            for (int i = 0; i < 8; ++i)
#pragma unroll
                for (int j = 0; j < 8; ++j) acc[i][j] = fmaf(a[i], bb[j], acc[i][j]);
        }
        const bool diag = (kt == qt), caus = (kt < qt);
#pragma unroll
        for (int ii = 0; ii < 8; ++ii) {
            const int i = qi0 + ty*8 + ii;
            float s[8]; float vmx = -1e30f, vmn = 1e30f;
#pragma unroll
            for (int jj = 0; jj < 8; ++jj) {
                s[jj] = acc[ii][jj] * SCALEF;
                vmn = fminf(vmn, s[jj]);
                bool val = caus || (diag && (kj0 + tx*8 + jj) <= i);
                if (val) vmx = fmaxf(vmx, s[jj]);
            }
#pragma unroll
            for (int o = 8; o >= 1; o >>= 1) {
                vmx = fmaxf(vmx, __shfl_xor_sync(0xffffffffu, vmx, o));
                vmn = fminf(vmn, __shfl_xor_sync(0xffffffffu, vmn, o));
            }
            run_mn[ii] = fminf(run_mn[ii], vmn);
            if (caus || diag) {
                float tl = 0.f;
#pragma unroll
                for (int jj = 0; jj < 8; ++jj) {
                    bool val = caus || ((kj0 + tx*8 + jj) <= i);
                    if (val) tl += __expf(s[jj] - vmx);
                }
#pragma unroll
                for (int o = 8; o >= 1; o >>= 1) tl += __shfl_xor_sync(0xffffffffu, tl, o);
                float nm = fmaxf(run_m[ii], vmx);
                run_l[ii] = run_l[ii] * __expf(run_m[ii] - nm) + tl * __expf(vmx - nm);
                run_m[ii] = nm;
                float* arow = attn + ((size_t)bh * SLEN + i) * SLEN + kj0 + tx*8;
                *reinterpret_cast<float4*>(arow)   = make_float4(s[0],s[1],s[2],s[3]);
                *reinterpret_cast<float4*>(arow+4) = make_float4(s[4],s[5],s[6],s[7]);
            }
        }
    }
    if (tx == 0) {
#pragma unroll
        for (int ii = 0; ii < 8; ++ii) {
            const int i = qi0 + ty*8 + ii;
            float m = run_m[ii];
            float e = __expf(run_mn[ii] - 20.f - m);
            float L = run_l[ii] + (float)(SLEN - 1 - i) * e;
            float id = 1.f / L;
            g_sm [(size_t)bh * SLEN + i] = m;
            g_sid[(size_t)bh * SLEN + i] = id;
            g_sc [(size_t)bh * SLEN + i] = e * id;
        }
    }
}

// -------- fill fully-masked tiles with per-row constant ---------------------
__global__ __launch_bounds__(256) void fill_masked(float* __restrict__ attn) {
    const int qt = blockIdx.x, bh = blockIdx.y;
    const int i0 = qt * 128, c0 = (qt + 1) * 128;
    const int nc4 = (SLEN - c0) >> 2;
    for (int r = 0; r < 128; ++r) {
        const int i = i0 + r;
        float c = g_sc[(size_t)bh * SLEN + i];
        float4 cv = make_float4(c, c, c, c);
        float4* row = reinterpret_cast<float4*>(attn + ((size_t)bh * SLEN + i) * SLEN + c0);
        for (int x = threadIdx.x; x < nc4; x += 256) row[x] = cv;
    }
}

// -------- pass B: finalize probs on causal tiles + PV + gate ----------------
__global__ __launch_bounds__(256, 1) void attn_pass_b(float* __restrict__ attn) {
    extern __shared__ float smemf[];
    float* ps = smemf;
    float* vs = smemf + 16384;
    const int tid = threadIdx.x, tx = tid & 15, ty = tid >> 4;
    const int qt = blockIdx.x, bh = blockIdx.y;
    const int b = bh >> 4, h = bh & 15, kh = h >> 1;
    const int qi0 = qt * 128;

    float m8[8], id8[8], c8[8];
#pragma unroll
    for (int ii = 0; ii < 8; ++ii) {
        size_t ri = (size_t)bh * SLEN + qi0 + ty*8 + ii;
        m8[ii] = g_sm[ri]; id8[ii] = g_sid[ri]; c8[ii] = g_sc[ri];
    }
    float acc[8][8];
#pragma unroll
    for (int i = 0; i < 8; ++i)
#pragma unroll
        for (int j = 0; j < 8; ++j) acc[i][j] = 0.f;

    const float* vb = g_vraw + (size_t)b * SLEN * KVW + (size_t)kh * HD;
    for (int kt = 0; kt <= qt; ++kt) {
        const int kj0 = kt * 128;
        __syncthreads();
#pragma unroll
        for (int it = 0; it < 16; ++it) {
            int slot = it * 256 + tid;
            int c = slot >> 5, d4 = (slot & 31) * 4;
            *reinterpret_cast<float4*>(&vs[c*128 + d4]) =
                *reinterpret_cast<const float4*>(vb + (size_t)(kj0 + c) * KVW + d4);
        }
        const bool diag = (kt == qt);
#pragma unroll
        for (int ii = 0; ii < 8; ++ii) {
            const int i = qi0 + ty*8 + ii;
            float* arow = attn + ((size_t)bh * SLEN + i) * SLEN + kj0 + tx*8;
            float4 s0 = *reinterpret_cast<const float4*>(arow);
            float4 s1 = *reinterpret_cast<const float4*>(arow + 4);
            float sv[8] = {s0.x, s0.y, s0.z, s0.w, s1.x, s1.y, s1.z, s1.w};
            float pw[8], pp[8];
#pragma unroll
            for (int jj = 0; jj < 8; ++jj) {
                float e = __expf(sv[jj] - m8[ii]) * id8[ii];
                bool val = !diag || ((kj0 + tx*8 + jj) <= i);
                pw[jj] = val ? e : c8[ii];
                pp[jj] = val ? e : 0.f;
            }
            *reinterpret_cast<float4*>(arow)   = make_float4(pw[0],pw[1],pw[2],pw[3]);
            *reinterpret_cast<float4*>(arow+4) = make_float4(pw[4],pw[5],pw[6],pw[7]);
            float* prow = &ps[(ty*8 + ii) * 128 + tx*8];
            *reinterpret_cast<float4*>(prow)   = make_float4(pp[0],pp[1],pp[2],pp[3]);
            *reinterpret_cast<float4*>(prow+4) = make_float4(pp[4],pp[5],pp[6],pp[7]);
        }
        __syncthreads();
#pragma unroll 4
        for (int j = 0; j < 128; ++j) {
            float a[8], bb[8];
#pragma unroll
            for (int ii = 0; ii < 8; ++ii) a[ii] = ps[(ty*8 + ii) * 128 + j];
            *reinterpret_cast<float4*>(&bb[0]) = *reinterpret_cast<const float4*>(&vs[j*128 + tx*8]);
            *reinterpret_cast<float4*>(&bb[4]) = *reinterpret_cast<const float4*>(&vs[j*128 + tx*8 + 4]);
#pragma unroll
            for (int ii = 0; ii < 8; ++ii)
#pragma unroll
                for (int dd = 0; dd < 8; ++dd) acc[ii][dd] = fmaf(a[ii], bb[dd], acc[ii][dd]);
        }
    }
#pragma unroll
    for (int ii = 0; ii < 8; ++ii) {
        const int i = qi0 + ty*8 + ii;
        const float* vsf  = g_vsuf + (((size_t)(b * NKV + kh)) * SLEN + i) * HD + tx*8;
        const float* grow = g_gate + ((size_t)b * SLEN + i) * OWID + (size_t)h * HD + tx*8;
        float*       orow = g_ao   + ((size_t)b * SLEN + i) * OWID + (size_t)h * HD + tx*8;
        float o[8];
#pragma unroll
        for (int dd = 0; dd < 8; ++dd) {
            float val = acc[ii][dd] + c8[ii] * vsf[dd];
            o[dd] = val / (1.f + __expf(-grow[dd]));
        }
        *reinterpret_cast<float4*>(orow)   = make_float4(o[0],o[1],o[2],o[3]);
        *reinterpret_cast<float4*>(orow+4) = make_float4(o[4],o[5],o[6],o[7]);
    }
}

// ----------------------------------------------------------------------------
extern "C" void kernel_launch(void* const* d_in, const int* in_sizes, int n_in,
                              void* d_out, int out_size) {
    const float* hidden = (const float*)d_in[0];
    const float* cosb   = (const float*)d_in[1];
    const float* sinb   = (const float*)d_in[2];
    const float* Wq     = (const float*)d_in[4];
    const float* Wk     = (const float*)d_in[5];
    const float* Wv     = (const float*)d_in[6];
    const float* Wo     = (const float*)d_in[7];
    const float* qnw    = (const float*)d_in[8];
    const float* knw    = (const float*)d_in[9];

    float* out_ptr  = (float*)d_out;
    float* attn_ptr = out_ptr + (size_t)NBATCH * SLEN * HDIM;

    float *p_qraw, *p_kraw, *p_vraw, *p_ao;
    cudaGetSymbolAddress((void**)&p_qraw, g_qraw);
    cudaGetSymbolAddress((void**)&p_kraw, g_kraw);
    cudaGetSymbolAddress((void**)&p_vraw, g_vraw);
    cudaGetSymbolAddress((void**)&p_ao,   g_ao);

    cudaFuncSetAttribute(gemm_tc,     cudaFuncAttributeMaxDynamicSharedMemorySize, GEMM_SMEM);
    cudaFuncSetAttribute(attn_pass_a, cudaFuncAttributeMaxDynamicSharedMemorySize, 131072);
    cudaFuncSetAttribute(attn_pass_b, cudaFuncAttributeMaxDynamicSharedMemorySize, 131072);

    // QKV projections (HMMA fp16x3)
    gemm_tc<<<dim3(2*OWID/128, TTOK/128), 256, GEMM_SMEM>>>(hidden, Wq, p_qraw, TTOK, 2*OWID, HDIM);
    gemm_tc<<<dim3(KVW/128,    TTOK/128), 256, GEMM_SMEM>>>(hidden, Wk, p_kraw, TTOK, KVW,    HDIM);
    gemm_tc<<<dim3(KVW/128,    TTOK/128), 256, GEMM_SMEM>>>(hidden, Wv, p_vraw, TTOK, KVW,    HDIM);

    // norms + rope + gate split
    postq<<<TTOK * NH,  128>>>(cosb, sinb, qnw);
    postk<<<TTOK * NKV, 128>>>(cosb, sinb, knw);

    // V suffix sums
    vsuf_chunks<<<NBATCH * NKV * NCH, 128>>>();
    vsuf_write <<<NBATCH * NKV * NCH, 128>>>();

    // attention
    attn_pass_a<<<dim3(SLEN/128, BH), 256, 131072>>>(attn_ptr);
    fill_masked<<<dim3(SLEN/128 - 1, BH), 256>>>(attn_ptr);
    attn_pass_b<<<dim3(SLEN/128, BH), 256, 131072>>>(attn_ptr);

    // output projection (HMMA fp16x3)
    gemm_tc<<<dim3(HDIM/128, TTOK/128), 256, GEMM_SMEM>>>(p_ao, Wo, out_ptr, TTOK, HDIM, OWID);
}